// round 10
// baseline (speedup 1.0000x reference)
#include <cuda_runtime.h>
#include <cuda_fp16.h>
#include <math.h>
#include <stdint.h>

// ---------------- problem constants ----------------
#define NB   128
#define LT   256
#define FH   768
#define GG   3072
#define BG   (NB*LT)

// ---- big hoisted GEMM (fp16 2-term) ----
#define K2   (2*FH)          // 1536
#define BK   32
#define NK2  (K2/BK)         // 48
#define ROWB 80
#define ATILE (128*ROWB)
#define STAGEB (2*ATILE)     // 20480
#define GNST 8               // producer-role stages

// ---- persistent recurrent role (fp16 3-term, reuse-A) ----
#define KR2   1536           // h packed [hh|hl]
#define RBK   64
#define RNCH  24             // 12 hh + 12 hl chunks
#define RROW  144
#define RA_BY (128*RROW)     // 18432 per A stage
#define RNST  4
#define WCHB  (32*RROW)      // 4608 per W chunk
#define WBASE (RNST*RA_BY)   // 73728
#define PSMEM (WBASE + RNCH*WCHB)   // 184320
#define NRB   96             // lstm-role blocks
#define NGB   52             // gemm-role blocks
#define NTILE (24*LT)        // 6144 gemm tiles
#define MEGA_SMEM PSMEM

// ---------------- scratch (device globals) ----------------
__device__ __half g_Xp [(size_t)BG * K2];
__device__ __half g_Wp [(size_t)GG * K2];
__device__ __half g_Whp[(size_t)GG * KR2];
__device__ __half g_hp [2][(size_t)NB * KR2];
__device__ float  g_XW [(size_t)BG * GG];
__device__ int    g_flag[LT];        // xw tiles ready per timestep (0..24)
__device__ int    g_hflag[LT][12];   // h slice groups ready per timestep (0..8)

__constant__ int c_par[24] = {-1,0,0,0,1,2,3,4,5,6,7,8,9,9,9,12,13,14,16,17,18,19,20,21};

__device__ __forceinline__ float sigm(float x) { return 1.f / (1.f + expf(-x)); }

__device__ __forceinline__ uint32_t smem_u32(const void* p) {
    uint32_t a;
    asm("{ .reg .u64 t; cvta.to.shared.u64 t, %1; cvt.u32.u64 %0, t; }" : "=r"(a) : "l"(p));
    return a;
}

__device__ __forceinline__ void cp16(uint32_t s, const void* g) {
    asm volatile("cp.async.cg.shared.global [%0], [%1], 16;" :: "r"(s), "l"(g));
}

__device__ __forceinline__ void ldm_x4(uint32_t &r0, uint32_t &r1, uint32_t &r2,
                                       uint32_t &r3, uint32_t addr) {
    asm volatile("ldmatrix.sync.aligned.m8n8.x4.shared.b16 {%0,%1,%2,%3}, [%4];"
                 : "=r"(r0), "=r"(r1), "=r"(r2), "=r"(r3) : "r"(addr));
}

__device__ __forceinline__ void mma_f16(float* d, const uint32_t* a,
                                        const uint32_t* b) {
    asm volatile(
        "mma.sync.aligned.m16n8k16.row.col.f32.f16.f16.f32 "
        "{%0,%1,%2,%3}, {%4,%5,%6,%7}, {%8,%9}, {%0,%1,%2,%3};"
        : "+f"(d[0]), "+f"(d[1]), "+f"(d[2]), "+f"(d[3])
        : "r"(a[0]), "r"(a[1]), "r"(a[2]), "r"(a[3]), "r"(b[0]), "r"(b[1]));
}

// ---------------- small prep kernels ----------------
__global__ void reset_flags() {
    int i = blockIdx.x * 256 + threadIdx.x;
    if (i < LT) g_flag[i] = 0;
    if (i < LT * 12) ((int*)g_hflag)[i] = 0;
}

__global__ void pack_w(const float* __restrict__ W, __half* __restrict__ Wp) {
    int i = blockIdx.x * 256 + threadIdx.x;
    if (i >= GG * FH) return;
    int n = i / FH, k = i % FH;
    __half wh = __float2half(W[i]);
    size_t o = (size_t)n * K2 + k;
    Wp[o] = wh; Wp[o + FH] = wh;
}

__global__ void pack_whh(const float* __restrict__ W) {
    size_t idx = (size_t)blockIdx.x * 256 + threadIdx.x;
    if (idx >= (size_t)GG * KR2) return;
    int k   = (int)(idx % KR2);
    int row = (int)(idx / KR2);
    int b = row >> 5, r = row & 31;
    int g = r >> 3, fi = r & 7;
    int seg = k / FH, kk = k % FH;
    float w = W[(size_t)(g * FH + b * 8 + fi) * FH + kk];
    __half wh = __float2half(w);
    g_Whp[idx] = (seg == 0) ? wh : __float2half(w - __half2float(wh));
}

// ---------------- GAT: one warp per graph, packs [ah | al] ----------------
__global__ __launch_bounds__(256) void gat_kernel(
    const float* __restrict__ src,
    const float* __restrict__ W_pre, const float* __restrict__ b_pre,
    const float* __restrict__ W_gat,
    const float* __restrict__ att_src, const float* __restrict__ att_dst,
    const float* __restrict__ b_gat,
    __half* __restrict__ Xp)
{
    __shared__ float Wg[32 * 32];
    __shared__ float xbuf[8][24][32];
    __shared__ float asd[8][24][2];

    int tid = threadIdx.x;
    for (int i = tid; i < 1024; i += 256) Wg[i] = W_gat[i];
    __syncthreads();

    int w = tid >> 5, h = tid & 31;
    int b = blockIdx.x * 8 + w;
    int n = b >> 8, l = b & 255;

    const float* s = src + (size_t)b * 72;
    float w0 = W_pre[h], w1 = W_pre[32 + h], w2 = W_pre[64 + h], bp = b_pre[h];

    #pragma unroll
    for (int j = 0; j < 24; j++) {
        float v = fmaf(s[j*3+2], w2, fmaf(s[j*3+1], w1, fmaf(s[j*3+0], w0, bp)));
        xbuf[w][j][h] = tanhf(v);
    }
    __syncwarp();

    float asrc = att_src[h], adst = att_dst[h];
    #pragma unroll
    for (int j = 0; j < 24; j++) {
        float acc = 0.f;
        #pragma unroll
        for (int k = 0; k < 32; k++) acc = fmaf(xbuf[w][j][k], Wg[k*32 + h], acc);
        float ps = acc * asrc, pd = acc * adst;
        #pragma unroll
        for (int o = 16; o > 0; o >>= 1) {
            ps += __shfl_xor_sync(0xffffffffu, ps, o);
            pd += __shfl_xor_sync(0xffffffffu, pd, o);
        }
        __syncwarp();
        xbuf[w][j][h] = acc;
        if (h == 0) { asd[w][j][0] = ps; asd[w][j][1] = pd; }
    }
    __syncwarp();

    float bg = b_gat[h];
    size_t rbase = (size_t)(l * 128 + n) * K2;
    #pragma unroll
    for (int j = 0; j < 24; j++) {
        int p = c_par[j];
        float g;
        if (p < 0) {
            g = xbuf[w][j][h];
        } else {
            float ad = asd[w][j][1];
            float es = ad + asd[w][j][0];
            float ep = ad + asd[w][p][0];
            es = es > 0.f ? es : 0.2f * es;
            ep = ep > 0.f ? ep : 0.2f * ep;
            float m  = fmaxf(es, ep);
            float ws = expf(es - m), wp = expf(ep - m);
            float inv = 1.f / (ws + wp);
            g = (ws * xbuf[w][j][h] + wp * xbuf[w][p][h]) * inv;
        }
        float v = g + bg;
        __half vh = __float2half(v);
        size_t o = rbase + j * 32 + h;
        Xp[o]      = vh;
        Xp[o + FH] = __float2half(v - __half2float(vh));
    }
}

// ---------------- mega kernel: producer gemm (52) + dataflow LSTM (96) -------
__global__ __launch_bounds__(256, 1) void mega(
    const float* __restrict__ bih, const float* __restrict__ bhh,
    float* __restrict__ out)
{
    extern __shared__ __align__(16) char sm[];
    const uint32_t smb = smem_u32(sm);

    const int tid  = threadIdx.x;
    const int lane = tid & 31;
    const int warp = tid >> 5;

    if (blockIdx.x >= NRB) {
        // ================= producer role =================
        const int gb = blockIdx.x - NRB;
        const __half* Ap = g_Xp;
        const __half* Bp = g_Wp;
        float* C = g_XW;

        const int wm = warp >> 2;
        const int wn = warp & 3;
        const int ldRow = tid >> 2;
        const int ldSeg = tid & 3;
        const uint32_t stRow = ldRow * ROWB + ldSeg * 16;
        const uint32_t aOff = (uint32_t)((wm * 64 + (lane & 7) + ((lane >> 3) & 1) * 8) * ROWB
                                         + ((lane >> 4) & 1) * 16);
        const uint32_t bOff = (uint32_t)(ATILE + (wn * 32 + (lane & 7) + ((lane >> 4) & 1) * 8) * ROWB
                                         + ((lane >> 3) & 1) * 16);

        for (int tile = gb; tile < NTILE; tile += NGB) {
            const int y = tile / 24;
            const int x = tile % 24;
            const int m0 = y * 128;
            const int n0 = x * 128;

            const __half* gA = Ap + (size_t)(m0 + ldRow) * K2 + ldSeg * 8;
            const __half* gB = Bp + (size_t)(n0 + ldRow) * K2 + ldSeg * 8;

            float acc[4][4][4];
            #pragma unroll
            for (int i = 0; i < 4; i++)
                #pragma unroll
                for (int j = 0; j < 4; j++)
                    #pragma unroll
                    for (int q = 0; q < 4; q++) acc[i][j][q] = 0.f;

            #pragma unroll
            for (int pc = 0; pc < GNST - 1; pc++) {
                uint32_t sb = smb + pc * STAGEB;
                int ko = pc * BK;
                #pragma unroll
                for (int i = 0; i < 2; i++) {
                    cp16(sb + stRow + i * 64 * ROWB,         gA + (size_t)i * 64 * K2 + ko);
                    cp16(sb + ATILE + stRow + i * 64 * ROWB, gB + (size_t)i * 64 * K2 + ko);
                }
                asm volatile("cp.async.commit_group;");
            }

            for (int kc = 0; kc < NK2; kc++) {
                asm volatile("cp.async.wait_group %0;" :: "n"(GNST - 2));
                __syncthreads();

                if (kc + GNST - 1 < NK2) {
                    uint32_t sb = smb + ((kc + GNST - 1) & (GNST - 1)) * STAGEB;
                    int ko = (kc + GNST - 1) * BK;
                    #pragma unroll
                    for (int i = 0; i < 2; i++) {
                        cp16(sb + stRow + i * 64 * ROWB,         gA + (size_t)i * 64 * K2 + ko);
                        cp16(sb + ATILE + stRow + i * 64 * ROWB, gB + (size_t)i * 64 * K2 + ko);
                    }
                }
                asm volatile("cp.async.commit_group;");

                const uint32_t soff = smb + (kc & (GNST - 1)) * STAGEB;
                #pragma unroll
                for (int ks = 0; ks < 2; ks++) {
                    uint32_t a[4][4], bq[4][2];
                    #pragma unroll
                    for (int tm = 0; tm < 4; tm++)
                        ldm_x4(a[tm][0], a[tm][1], a[tm][2], a[tm][3],
                               soff + aOff + tm * (16 * ROWB) + ks * 32);
                    #pragma unroll
                    for (int tb = 0; tb < 2; tb++) {
                        uint32_t r0, r1, r2, r3;
                        ldm_x4(r0, r1, r2, r3, soff + bOff + tb * (16 * ROWB) + ks * 32);
                        bq[2*tb][0] = r0; bq[2*tb][1] = r1;
                        bq[2*tb+1][0] = r2; bq[2*tb+1][1] = r3;
                    }
                    #pragma unroll
                    for (int tm = 0; tm < 4; tm++)
                        #pragma unroll
                        for (int tn = 0; tn < 4; tn++)
                            mma_f16(acc[tm][tn], a[tm], bq[tn]);
                }
            }
            asm volatile("cp.async.wait_group 0;");

            #pragma unroll
            for (int tm = 0; tm < 4; tm++) {
                int row = m0 + wm * 64 + tm * 16 + (lane >> 2);
                #pragma unroll
                for (int tn = 0; tn < 4; tn++) {
                    int col = n0 + wn * 32 + tn * 8 + (lane & 3) * 2;
                    float* p = C + (size_t)row * GG + col;
                    *(float2*)p                    = make_float2(acc[tm][tn][0], acc[tm][tn][1]);
                    *(float2*)(p + (size_t)8 * GG) = make_float2(acc[tm][tn][2], acc[tm][tn][3]);
                }
            }

            __threadfence();
            __syncthreads();
            if (tid == 0) atomicAdd(&g_flag[y], 1);
            __syncthreads();
        }
        return;
    }

    // ================= consumer role: dataflow persistent LSTM =================
    const int wm = warp >> 1;
    const int wn = warp & 1;
    const int b  = blockIdx.x;

    const int efi = tid & 7;
    const int em0 = tid >> 3;
    const int feat = b * 8 + efi;

    // one-time resident W slice
    {
        const __half* Wb = g_Whp + (size_t)b * 32 * KR2;
        for (int i = tid; i < RNCH * 256; i += 256) {
            int chunk = i >> 8;
            int rem   = i & 255;
            int row   = rem >> 3, seg = rem & 7;
            cp16(smb + WBASE + chunk * WCHB + row * RROW + seg * 16,
                 Wb + (size_t)row * KR2 + chunk * RBK + seg * 8);
        }
        asm volatile("cp.async.commit_group;");
        asm volatile("cp.async.wait_group 0;");
    }

    float bias_r[4];
    #pragma unroll
    for (int g = 0; g < 4; g++) bias_r[g] = bih[g * FH + feat] + bhh[g * FH + feat];

    float creg[4] = {0.f, 0.f, 0.f, 0.f};

    __syncthreads();

    const uint32_t aOff = (uint32_t)((wm * 32 + (lane & 15)) * RROW
                                     + ((lane >> 4) & 1) * 16);
    const uint32_t bOffW = (uint32_t)((wn * 16 + (lane & 7) + ((lane >> 4) & 1) * 8) * RROW
                                      + ((lane >> 3) & 1) * 16);

    const float* xwbase = g_XW;

    for (int t = 0; t < LT; t++) {
        const __half* hin   = g_hp[(t + 1) & 1];
        __half*       houtp = g_hp[t & 1];
        const float*  xw    = xwbase + (size_t)t * NB * GG;

        // ---- wait for xw[t] tiles ----
        if (tid == 0) {
            while (*(volatile int*)&g_flag[t] < 24) { __nanosleep(128); }
            __threadfence();
        }
        __syncthreads();

        float xwv[4][4];
        #pragma unroll
        for (int i = 0; i < 4; i++) {
            const float* xwr = xw + (size_t)(em0 + i * 32) * GG + feat;
            xwv[i][0] = xwr[0];
            xwv[i][1] = xwr[FH];
            xwv[i][2] = xwr[2 * FH];
            xwv[i][3] = xwr[3 * FH];
        }

        float acc[2][2][4];
        #pragma unroll
        for (int i = 0; i < 2; i++)
            #pragma unroll
            for (int j = 0; j < 2; j++)
                #pragma unroll
                for (int q = 0; q < 4; q++) acc[i][j][q] = 0.f;

        if (t > 0) {
            unsigned hdone = 0;                      // groups observed complete
            const int* hf = g_hflag[t - 1];

            #define WAITG(gid_) do {                                          \
                unsigned _m = 1u << (gid_);                                   \
                if (!(hdone & _m)) {                                          \
                    while (*(volatile int*)&hf[(gid_)] < 8) __nanosleep(64);  \
                    __threadfence();                                          \
                    hdone |= _m;                                              \
                }                                                             \
            } while (0)

            #pragma unroll
            for (int pc = 0; pc < RNST - 1; pc++) {
                WAITG(pc);
                uint32_t sb = smb + pc * RA_BY;
                int ko = pc * RBK;
                #pragma unroll
                for (int i = 0; i < 4; i++) {
                    int slot = tid + i * 256;
                    int row = slot >> 3, seg = slot & 7;
                    cp16(sb + row * RROW + seg * 16,
                         hin + (size_t)row * KR2 + ko + seg * 8);
                }
                asm volatile("cp.async.commit_group;");
            }

            for (int kc = 0; kc < RNCH; kc++) {
                asm volatile("cp.async.wait_group %0;" :: "n"(RNST - 2));
                __syncthreads();

                if (kc + RNST - 1 < RNCH) {
                    int nc = kc + RNST - 1;
                    int gid = (nc < 12) ? nc : nc - 12;
                    WAITG(gid);
                    uint32_t sb = smb + (nc & (RNST - 1)) * RA_BY;
                    int ko = nc * RBK;
                    #pragma unroll
                    for (int i = 0; i < 4; i++) {
                        int slot = tid + i * 256;
                        int row = slot >> 3, seg = slot & 7;
                        cp16(sb + row * RROW + seg * 16,
                             hin + (size_t)row * KR2 + ko + seg * 8);
                    }
                }
                asm volatile("cp.async.commit_group;");

                const uint32_t soff = smb + (kc & (RNST - 1)) * RA_BY;
                const bool two = (kc < 12);
                const uint32_t woffH = smb + WBASE + (two ? kc : kc - 12) * WCHB;
                const uint32_t woffL = smb + WBASE + (kc + 12) * WCHB;

                #pragma unroll
                for (int ks = 0; ks < RBK / 16; ks++) {
                    uint32_t a[2][4], bq[2][2];
                    #pragma unroll
                    for (int tm = 0; tm < 2; tm++)
                        ldm_x4(a[tm][0], a[tm][1], a[tm][2], a[tm][3],
                               soff + aOff + tm * (16 * RROW) + ks * 32);
                    {
                        uint32_t r0, r1, r2, r3;
                        ldm_x4(r0, r1, r2, r3, woffH + bOffW + ks * 32);
                        bq[0][0] = r0; bq[0][1] = r1;
                        bq[1][0] = r2; bq[1][1] = r3;
                    }
                    #pragma unroll
                    for (int tm = 0; tm < 2; tm++)
                        #pragma unroll
                        for (int tn = 0; tn < 2; tn++)
                            mma_f16(acc[tm][tn], a[tm], bq[tn]);

                    if (two) {
                        uint32_t r0, r1, r2, r3;
                        ldm_x4(r0, r1, r2, r3, woffL + bOffW + ks * 32);
                        bq[0][0] = r0; bq[0][1] = r1;
                        bq[1][0] = r2; bq[1][1] = r3;
                        #pragma unroll
                        for (int tm = 0; tm < 2; tm++)
                            #pragma unroll
                            for (int tn = 0; tn < 2; tn++)
                                mma_f16(acc[tm][tn], a[tm], bq[tn]);
                    }
                }
            }
            asm volatile("cp.async.wait_group 0;");
            #undef WAITG
        }
        __syncthreads();

        float* Gt = (float*)sm;
        #pragma unroll
        for (int tm = 0; tm < 2; tm++) {
            int m = wm * 32 + tm * 16 + (lane >> 2);
            #pragma unroll
            for (int tn = 0; tn < 2; tn++) {
                int n = wn * 16 + tn * 8 + (lane & 3) * 2;
                Gt[n * 132 + m]           = acc[tm][tn][0];
                Gt[(n + 1) * 132 + m]     = acc[tm][tn][1];
                Gt[n * 132 + m + 8]       = acc[tm][tn][2];
                Gt[(n + 1) * 132 + m + 8] = acc[tm][tn][3];
            }
        }
        __syncthreads();

        #pragma unroll
        for (int i = 0; i < 4; i++) {
            int m = em0 + i * 32;

            float gi = Gt[(0*8 + efi) * 132 + m] + xwv[i][0] + bias_r[0];
            float gf = Gt[(1*8 + efi) * 132 + m] + xwv[i][1] + bias_r[1];
            float gg = Gt[(2*8 + efi) * 132 + m] + xwv[i][2] + bias_r[2];
            float go = Gt[(3*8 + efi) * 132 + m] + xwv[i][3] + bias_r[3];

            float c  = sigm(gf) * creg[i] + sigm(gi) * tanhf(gg);
            float hv = sigm(go) * tanhf(c);
            creg[i] = c;

            out[((size_t)m * LT + t) * FH + feat] = hv;

            __half hh = __float2half(hv);
            size_t hb = (size_t)m * KR2 + feat;
            houtp[hb]      = hh;
            houtp[hb + FH] = __float2half(hv - __half2float(hh));

            if (t == LT - 1) {
                out[(size_t)NB * LT * FH + (size_t)m * FH + feat]           = hv;
                out[(size_t)NB * LT * FH + NB * FH + (size_t)m * FH + feat] = c;
            }
        }

        // ---- publish this block's h slice (release) ----
        __threadfence();
        __syncthreads();          // all threads' stores + fences done; smem safe to reuse
        if (tid == 0) atomicAdd(&g_hflag[t][b >> 3], 1);
    }
}

// ---------------- launch ----------------
extern "C" void kernel_launch(void* const* d_in, const int* in_sizes, int n_in,
                              void* d_out, int out_size)
{
    const float* src     = (const float*)d_in[0];
    const float* W_pre   = (const float*)d_in[1];
    const float* b_pre   = (const float*)d_in[2];
    const float* W_gat   = (const float*)d_in[3];
    const float* att_src = (const float*)d_in[4];
    const float* att_dst = (const float*)d_in[5];
    const float* b_gat   = (const float*)d_in[6];
    const float* W_ih    = (const float*)d_in[7];
    const float* W_hh    = (const float*)d_in[8];
    const float* b_ih    = (const float*)d_in[9];
    const float* b_hh    = (const float*)d_in[10];
    float* out = (float*)d_out;

    __half *Xp, *Wp;
    cudaGetSymbolAddress((void**)&Xp,  g_Xp);
    cudaGetSymbolAddress((void**)&Wp,  g_Wp);

    cudaFuncSetAttribute(mega, cudaFuncAttributeMaxDynamicSharedMemorySize,
                         MEGA_SMEM);

    // 0) prep
    reset_flags<<<13, 256>>>();
    pack_w<<<(GG * FH + 255) / 256, 256>>>(W_ih, Wp);
    pack_whh<<<(unsigned)(((size_t)GG * KR2 + 255) / 256), 256>>>(W_hh);

    // 1) GAT -> packed fp16 X
    gat_kernel<<<BG / 8, 256>>>(src, W_pre, b_pre, W_gat, att_src, att_dst, b_gat, Xp);

    // 2) fused producer-GEMM + dataflow persistent-LSTM
    mega<<<NRB + NGB, 256, MEGA_SMEM>>>(b_ih, b_hh, out);
}

// round 11
// speedup vs baseline: 1.7422x; 1.7422x over previous
#include <cuda_runtime.h>
#include <cuda_fp16.h>
#include <math.h>
#include <stdint.h>

// ---------------- problem constants ----------------
#define NB   128
#define LT   256
#define FH   768
#define GG   3072
#define BG   (NB*LT)

// ---- big hoisted GEMM (fp16 2-term) ----
#define K2   (2*FH)          // 1536
#define BK   32
#define NK2  (K2/BK)         // 48
#define ROWB 80
#define ATILE (128*ROWB)
#define STAGEB (2*ATILE)     // 20480
#define GNST 8               // producer-role stages

// ---- persistent recurrent role (fp16 2-term: h exact, W_hh rounded) ----
#define KR2   1536           // h packed [hh|hl]
#define RBK   64
#define RNCH  24             // 24 A chunks (12 hh + 12 hl)
#define NWCH  12             // 12 W chunks (wh only)
#define RROW  144
#define RA_BY (128*RROW)     // 18432 per A stage
#define RNST  6              // deeper pipeline (W smem halved)
#define WCHB  (32*RROW)      // 4608 per W chunk
#define WBASE (RNST*RA_BY)   // 110592
#define PSMEM (WBASE + NWCH*WCHB)   // 110592+55296 = 165888
#define NRB   96             // lstm-role blocks
#define NGB   52             // gemm-role blocks
#define NTILE (24*LT)        // 6144 gemm tiles
#define MEGA_SMEM PSMEM      // >= GNST*STAGEB (163840)

// ---------------- scratch (device globals) ----------------
__device__ __half g_Xp [(size_t)BG * K2];
__device__ __half g_Wp [(size_t)GG * K2];
__device__ __half g_Whp[(size_t)GG * FH];     // permuted W_hh (fp16, rounded)
__device__ __half g_hp [2][(size_t)NB * KR2]; // ping-pong packed h [hh|hl]
__device__ float  g_XW [(size_t)BG * GG];
__device__ unsigned g_ctr;                    // consumer grid barrier
__device__ int      g_flag[LT];               // xw tiles ready per timestep

__constant__ int c_par[24] = {-1,0,0,0,1,2,3,4,5,6,7,8,9,9,9,12,13,14,16,17,18,19,20,21};

__device__ __forceinline__ float sigm(float x) { return 1.f / (1.f + expf(-x)); }

__device__ __forceinline__ uint32_t smem_u32(const void* p) {
    uint32_t a;
    asm("{ .reg .u64 t; cvta.to.shared.u64 t, %1; cvt.u32.u64 %0, t; }" : "=r"(a) : "l"(p));
    return a;
}

__device__ __forceinline__ void cp16(uint32_t s, const void* g) {
    asm volatile("cp.async.cg.shared.global [%0], [%1], 16;" :: "r"(s), "l"(g));
}

__device__ __forceinline__ void ldm_x4(uint32_t &r0, uint32_t &r1, uint32_t &r2,
                                       uint32_t &r3, uint32_t addr) {
    asm volatile("ldmatrix.sync.aligned.m8n8.x4.shared.b16 {%0,%1,%2,%3}, [%4];"
                 : "=r"(r0), "=r"(r1), "=r"(r2), "=r"(r3) : "r"(addr));
}

__device__ __forceinline__ void mma_f16(float* d, const uint32_t* a,
                                        const uint32_t* b) {
    asm volatile(
        "mma.sync.aligned.m16n8k16.row.col.f32.f16.f16.f32 "
        "{%0,%1,%2,%3}, {%4,%5,%6,%7}, {%8,%9}, {%0,%1,%2,%3};"
        : "+f"(d[0]), "+f"(d[1]), "+f"(d[2]), "+f"(d[3])
        : "r"(a[0]), "r"(a[1]), "r"(a[2]), "r"(a[3]), "r"(b[0]), "r"(b[1]));
}

// ---------------- small prep kernels ----------------
__global__ void reset_flags() {
    int i = threadIdx.x;
    if (i == 0) g_ctr = 0u;
    if (i < LT) g_flag[i] = 0;
}

__global__ void pack_w(const float* __restrict__ W, __half* __restrict__ Wp) {
    int i = blockIdx.x * 256 + threadIdx.x;
    if (i >= GG * FH) return;
    int n = i / FH, k = i % FH;
    __half wh = __float2half(W[i]);
    size_t o = (size_t)n * K2 + k;
    Wp[o] = wh; Wp[o + FH] = wh;
}

// Block b owns local rows r = g*8 + fi <-> W_hh row (g*768 + b*8 + fi).
__global__ void pack_whh(const float* __restrict__ W) {
    size_t idx = (size_t)blockIdx.x * 256 + threadIdx.x;
    if (idx >= (size_t)GG * FH) return;
    int k   = (int)(idx % FH);
    int row = (int)(idx / FH);       // b*32 + r
    int b = row >> 5, r = row & 31;
    int g = r >> 3, fi = r & 7;
    g_Whp[idx] = __float2half(W[(size_t)(g * FH + b * 8 + fi) * FH + k]);
}

// ---------------- GAT: one warp per graph, packs [ah | al] ----------------
__global__ __launch_bounds__(256) void gat_kernel(
    const float* __restrict__ src,
    const float* __restrict__ W_pre, const float* __restrict__ b_pre,
    const float* __restrict__ W_gat,
    const float* __restrict__ att_src, const float* __restrict__ att_dst,
    const float* __restrict__ b_gat,
    __half* __restrict__ Xp)
{
    __shared__ float Wg[32 * 32];
    __shared__ float xbuf[8][24][32];
    __shared__ float asd[8][24][2];

    int tid = threadIdx.x;
    for (int i = tid; i < 1024; i += 256) Wg[i] = W_gat[i];
    __syncthreads();

    int w = tid >> 5, h = tid & 31;
    int b = blockIdx.x * 8 + w;
    int n = b >> 8, l = b & 255;

    const float* s = src + (size_t)b * 72;
    float w0 = W_pre[h], w1 = W_pre[32 + h], w2 = W_pre[64 + h], bp = b_pre[h];

    #pragma unroll
    for (int j = 0; j < 24; j++) {
        float v = fmaf(s[j*3+2], w2, fmaf(s[j*3+1], w1, fmaf(s[j*3+0], w0, bp)));
        xbuf[w][j][h] = tanhf(v);
    }
    __syncwarp();

    float asrc = att_src[h], adst = att_dst[h];
    #pragma unroll
    for (int j = 0; j < 24; j++) {
        float acc = 0.f;
        #pragma unroll
        for (int k = 0; k < 32; k++) acc = fmaf(xbuf[w][j][k], Wg[k*32 + h], acc);
        float ps = acc * asrc, pd = acc * adst;
        #pragma unroll
        for (int o = 16; o > 0; o >>= 1) {
            ps += __shfl_xor_sync(0xffffffffu, ps, o);
            pd += __shfl_xor_sync(0xffffffffu, pd, o);
        }
        __syncwarp();
        xbuf[w][j][h] = acc;
        if (h == 0) { asd[w][j][0] = ps; asd[w][j][1] = pd; }
    }
    __syncwarp();

    float bg = b_gat[h];
    size_t rbase = (size_t)(l * 128 + n) * K2;
    #pragma unroll
    for (int j = 0; j < 24; j++) {
        int p = c_par[j];
        float g;
        if (p < 0) {
            g = xbuf[w][j][h];
        } else {
            float ad = asd[w][j][1];
            float es = ad + asd[w][j][0];
            float ep = ad + asd[w][p][0];
            es = es > 0.f ? es : 0.2f * es;
            ep = ep > 0.f ? ep : 0.2f * ep;
            float m  = fmaxf(es, ep);
            float ws = expf(es - m), wp = expf(ep - m);
            float inv = 1.f / (ws + wp);
            g = (ws * xbuf[w][j][h] + wp * xbuf[w][p][h]) * inv;
        }
        float v = g + bg;
        __half vh = __float2half(v);
        size_t o = rbase + j * 32 + h;
        Xp[o]      = vh;
        Xp[o + FH] = __float2half(v - __half2float(vh));
    }
}

// ---------------- mega kernel: producer gemm (52) + persistent LSTM (96) -----
__global__ __launch_bounds__(256, 1) void mega(
    const float* __restrict__ bih, const float* __restrict__ bhh,
    float* __restrict__ out)
{
    extern __shared__ __align__(16) char sm[];
    const uint32_t smb = smem_u32(sm);

    const int tid  = threadIdx.x;
    const int lane = tid & 31;
    const int warp = tid >> 5;

    if (blockIdx.x >= NRB) {
        // ================= producer role =================
        const int gb = blockIdx.x - NRB;
        const __half* Ap = g_Xp;
        const __half* Bp = g_Wp;
        float* C = g_XW;

        const int wm = warp >> 2;
        const int wn = warp & 3;
        const int ldRow = tid >> 2;
        const int ldSeg = tid & 3;
        const uint32_t stRow = ldRow * ROWB + ldSeg * 16;
        const uint32_t aOff = (uint32_t)((wm * 64 + (lane & 7) + ((lane >> 3) & 1) * 8) * ROWB
                                         + ((lane >> 4) & 1) * 16);
        const uint32_t bOff = (uint32_t)(ATILE + (wn * 32 + (lane & 7) + ((lane >> 4) & 1) * 8) * ROWB
                                         + ((lane >> 3) & 1) * 16);

        for (int tile = gb; tile < NTILE; tile += NGB) {
            const int y = tile / 24;
            const int x = tile % 24;
            const int m0 = y * 128;
            const int n0 = x * 128;

            const __half* gA = Ap + (size_t)(m0 + ldRow) * K2 + ldSeg * 8;
            const __half* gB = Bp + (size_t)(n0 + ldRow) * K2 + ldSeg * 8;

            float acc[4][4][4];
            #pragma unroll
            for (int i = 0; i < 4; i++)
                #pragma unroll
                for (int j = 0; j < 4; j++)
                    #pragma unroll
                    for (int q = 0; q < 4; q++) acc[i][j][q] = 0.f;

            #pragma unroll
            for (int pc = 0; pc < GNST - 1; pc++) {
                uint32_t sb = smb + pc * STAGEB;
                int ko = pc * BK;
                #pragma unroll
                for (int i = 0; i < 2; i++) {
                    cp16(sb + stRow + i * 64 * ROWB,         gA + (size_t)i * 64 * K2 + ko);
                    cp16(sb + ATILE + stRow + i * 64 * ROWB, gB + (size_t)i * 64 * K2 + ko);
                }
                asm volatile("cp.async.commit_group;");
            }

            for (int kc = 0; kc < NK2; kc++) {
                asm volatile("cp.async.wait_group %0;" :: "n"(GNST - 2));
                __syncthreads();

                if (kc + GNST - 1 < NK2) {
                    uint32_t sb = smb + ((kc + GNST - 1) & (GNST - 1)) * STAGEB;
                    int ko = (kc + GNST - 1) * BK;
                    #pragma unroll
                    for (int i = 0; i < 2; i++) {
                        cp16(sb + stRow + i * 64 * ROWB,         gA + (size_t)i * 64 * K2 + ko);
                        cp16(sb + ATILE + stRow + i * 64 * ROWB, gB + (size_t)i * 64 * K2 + ko);
                    }
                }
                asm volatile("cp.async.commit_group;");

                const uint32_t soff = smb + (kc & (GNST - 1)) * STAGEB;
                #pragma unroll
                for (int ks = 0; ks < 2; ks++) {
                    uint32_t a[4][4], bq[4][2];
                    #pragma unroll
                    for (int tm = 0; tm < 4; tm++)
                        ldm_x4(a[tm][0], a[tm][1], a[tm][2], a[tm][3],
                               soff + aOff + tm * (16 * ROWB) + ks * 32);
                    #pragma unroll
                    for (int tb = 0; tb < 2; tb++) {
                        uint32_t r0, r1, r2, r3;
                        ldm_x4(r0, r1, r2, r3, soff + bOff + tb * (16 * ROWB) + ks * 32);
                        bq[2*tb][0] = r0; bq[2*tb][1] = r1;
                        bq[2*tb+1][0] = r2; bq[2*tb+1][1] = r3;
                    }
                    #pragma unroll
                    for (int tm = 0; tm < 4; tm++)
                        #pragma unroll
                        for (int tn = 0; tn < 4; tn++)
                            mma_f16(acc[tm][tn], a[tm], bq[tn]);
                }
            }
            asm volatile("cp.async.wait_group 0;");

            #pragma unroll
            for (int tm = 0; tm < 4; tm++) {
                int row = m0 + wm * 64 + tm * 16 + (lane >> 2);
                #pragma unroll
                for (int tn = 0; tn < 4; tn++) {
                    int col = n0 + wn * 32 + tn * 8 + (lane & 3) * 2;
                    float* p = C + (size_t)row * GG + col;
                    *(float2*)p                    = make_float2(acc[tm][tn][0], acc[tm][tn][1]);
                    *(float2*)(p + (size_t)8 * GG) = make_float2(acc[tm][tn][2], acc[tm][tn][3]);
                }
            }

            __threadfence();
            __syncthreads();
            if (tid == 0) atomicAdd(&g_flag[y], 1);
            __syncthreads();
        }
        return;
    }

    // ================= consumer role: persistent LSTM (2-term) =================
    const int wm = warp >> 1;
    const int wn = warp & 1;
    const int b  = blockIdx.x;

    const int efi = tid & 7;
    const int em0 = tid >> 3;
    const int feat = b * 8 + efi;

    // one-time resident W slice (12 chunks of wh)
    {
        const __half* Wb = g_Whp + (size_t)b * 32 * FH;
        for (int i = tid; i < NWCH * 256; i += 256) {
            int chunk = i >> 8;
            int rem   = i & 255;
            int row   = rem >> 3, seg = rem & 7;
            cp16(smb + WBASE + chunk * WCHB + row * RROW + seg * 16,
                 Wb + (size_t)row * FH + chunk * RBK + seg * 8);
        }
        asm volatile("cp.async.commit_group;");
        asm volatile("cp.async.wait_group 0;");
    }

    float bias_r[4];
    #pragma unroll
    for (int g = 0; g < 4; g++) bias_r[g] = bih[g * FH + feat] + bhh[g * FH + feat];

    float creg[4] = {0.f, 0.f, 0.f, 0.f};

    __syncthreads();

    const uint32_t aOff = (uint32_t)((wm * 32 + (lane & 15)) * RROW
                                     + ((lane >> 4) & 1) * 16);
    const uint32_t bOffW = (uint32_t)((wn * 16 + (lane & 7) + ((lane >> 4) & 1) * 8) * RROW
                                      + ((lane >> 3) & 1) * 16);

    unsigned* ctr = &g_ctr;
    const float* xwbase = g_XW;

    for (int t = 0; t < LT; t++) {
        const __half* hin   = g_hp[(t + 1) & 1];
        __half*       houtp = g_hp[t & 1];
        const float*  xw    = xwbase + (size_t)t * NB * GG;

        // ---- wait for xw[t] tiles ----
        if (tid == 0) {
            while (*(volatile int*)&g_flag[t] < 24) { __nanosleep(128); }
            __threadfence();
        }
        __syncthreads();

        float xwv[4][4];
        #pragma unroll
        for (int i = 0; i < 4; i++) {
            const float* xwr = xw + (size_t)(em0 + i * 32) * GG + feat;
            xwv[i][0] = xwr[0];
            xwv[i][1] = xwr[FH];
            xwv[i][2] = xwr[2 * FH];
            xwv[i][3] = xwr[3 * FH];
        }

        float acc[2][2][4];
        #pragma unroll
        for (int i = 0; i < 2; i++)
            #pragma unroll
            for (int j = 0; j < 2; j++)
                #pragma unroll
                for (int q = 0; q < 4; q++) acc[i][j][q] = 0.f;

        if (t > 0) {
            #pragma unroll
            for (int pc = 0; pc < RNST - 1; pc++) {
                uint32_t sb = smb + pc * RA_BY;
                int ko = pc * RBK;
                #pragma unroll
                for (int i = 0; i < 4; i++) {
                    int slot = tid + i * 256;
                    int row = slot >> 3, seg = slot & 7;
                    cp16(sb + row * RROW + seg * 16,
                         hin + (size_t)row * KR2 + ko + seg * 8);
                }
                asm volatile("cp.async.commit_group;");
            }

            int stage = 0;                      // = kc % RNST
            int pstage = RNST - 1;              // = (kc + RNST-1) % RNST
            for (int kc = 0; kc < RNCH; kc++) {
                asm volatile("cp.async.wait_group %0;" :: "n"(RNST - 2));
                __syncthreads();

                if (kc + RNST - 1 < RNCH) {
                    int nc = kc + RNST - 1;
                    uint32_t sb = smb + pstage * RA_BY;
                    int ko = nc * RBK;
                    #pragma unroll
                    for (int i = 0; i < 4; i++) {
                        int slot = tid + i * 256;
                        int row = slot >> 3, seg = slot & 7;
                        cp16(sb + row * RROW + seg * 16,
                             hin + (size_t)row * KR2 + ko + seg * 8);
                    }
                }
                asm volatile("cp.async.commit_group;");

                const uint32_t soff = smb + stage * RA_BY;
                const uint32_t woff = smb + WBASE + ((kc < NWCH) ? kc : kc - NWCH) * WCHB;

                #pragma unroll
                for (int ks = 0; ks < RBK / 16; ks++) {
                    uint32_t a[2][4], bq[2][2];
                    #pragma unroll
                    for (int tm = 0; tm < 2; tm++)
                        ldm_x4(a[tm][0], a[tm][1], a[tm][2], a[tm][3],
                               soff + aOff + tm * (16 * RROW) + ks * 32);
                    {
                        uint32_t r0, r1, r2, r3;
                        ldm_x4(r0, r1, r2, r3, woff + bOffW + ks * 32);
                        bq[0][0] = r0; bq[0][1] = r1;
                        bq[1][0] = r2; bq[1][1] = r3;
                    }
                    #pragma unroll
                    for (int tm = 0; tm < 2; tm++)
                        #pragma unroll
                        for (int tn = 0; tn < 2; tn++)
                            mma_f16(acc[tm][tn], a[tm], bq[tn]);
                }

                if (++stage == RNST) stage = 0;
                if (++pstage == RNST) pstage = 0;
            }
            asm volatile("cp.async.wait_group 0;");
        }
        __syncthreads();

        // gate tile overlay: Gt[32 n][132 m] fp32 (aliases A-stage smem)
        float* Gt = (float*)sm;
        #pragma unroll
        for (int tm = 0; tm < 2; tm++) {
            int m = wm * 32 + tm * 16 + (lane >> 2);
            #pragma unroll
            for (int tn = 0; tn < 2; tn++) {
                int n = wn * 16 + tn * 8 + (lane & 3) * 2;
                Gt[n * 132 + m]           = acc[tm][tn][0];
                Gt[(n + 1) * 132 + m]     = acc[tm][tn][1];
                Gt[n * 132 + m + 8]       = acc[tm][tn][2];
                Gt[(n + 1) * 132 + m + 8] = acc[tm][tn][3];
            }
        }
        __syncthreads();

        // pointwise: compute + publish h first, then arrive, then out stores
        float hvv[4];
        #pragma unroll
        for (int i = 0; i < 4; i++) {
            int m = em0 + i * 32;

            float gi = Gt[(0*8 + efi) * 132 + m] + xwv[i][0] + bias_r[0];
            float gf = Gt[(1*8 + efi) * 132 + m] + xwv[i][1] + bias_r[1];
            float gg = Gt[(2*8 + efi) * 132 + m] + xwv[i][2] + bias_r[2];
            float go = Gt[(3*8 + efi) * 132 + m] + xwv[i][3] + bias_r[3];

            float c  = sigm(gf) * creg[i] + sigm(gi) * tanhf(gg);
            float hv = sigm(go) * tanhf(c);
            creg[i] = c;
            hvv[i] = hv;

            __half hh = __float2half(hv);
            size_t hb = (size_t)m * KR2 + feat;
            houtp[hb]      = hh;
            houtp[hb + FH] = __float2half(hv - __half2float(hh));
        }

        // arrive: h slice published
        __threadfence();
        __syncthreads();
        if (tid == 0) atomicAdd(ctr, 1u);

        // out stores overlap other blocks' arrivals
        #pragma unroll
        for (int i = 0; i < 4; i++) {
            int m = em0 + i * 32;
            out[((size_t)m * LT + t) * FH + feat] = hvv[i];
            if (t == LT - 1) {
                out[(size_t)NB * LT * FH + (size_t)m * FH + feat]           = hvv[i];
                out[(size_t)NB * LT * FH + NB * FH + (size_t)m * FH + feat] = creg[i];
            }
        }

        // wait for all 96 consumer arrivals of step t
        if (tid == 0) {
            unsigned target = (unsigned)NRB * (unsigned)(t + 1);
            while (*(volatile unsigned*)ctr < target) { __nanosleep(64); }
            __threadfence();
        }
        __syncthreads();
    }
}

// ---------------- launch ----------------
extern "C" void kernel_launch(void* const* d_in, const int* in_sizes, int n_in,
                              void* d_out, int out_size)
{
    const float* src     = (const float*)d_in[0];
    const float* W_pre   = (const float*)d_in[1];
    const float* b_pre   = (const float*)d_in[2];
    const float* W_gat   = (const float*)d_in[3];
    const float* att_src = (const float*)d_in[4];
    const float* att_dst = (const float*)d_in[5];
    const float* b_gat   = (const float*)d_in[6];
    const float* W_ih    = (const float*)d_in[7];
    const float* W_hh    = (const float*)d_in[8];
    const float* b_ih    = (const float*)d_in[9];
    const float* b_hh    = (const float*)d_in[10];
    float* out = (float*)d_out;

    __half *Xp, *Wp;
    cudaGetSymbolAddress((void**)&Xp,  g_Xp);
    cudaGetSymbolAddress((void**)&Wp,  g_Wp);

    cudaFuncSetAttribute(mega, cudaFuncAttributeMaxDynamicSharedMemorySize,
                         MEGA_SMEM);

    // 0) prep
    reset_flags<<<1, 256>>>();
    pack_w<<<(GG * FH + 255) / 256, 256>>>(W_ih, Wp);
    pack_whh<<<(unsigned)(((size_t)GG * FH + 255) / 256), 256>>>(W_hh);

    // 1) GAT -> packed fp16 X
    gat_kernel<<<BG / 8, 256>>>(src, W_pre, b_pre, W_gat, att_src, att_dst, b_gat, Xp);

    // 2) fused producer-GEMM + persistent-LSTM
    mega<<<NRB + NGB, 256, MEGA_SMEM>>>(b_ih, b_hh, out);
}

// round 12
// speedup vs baseline: 2.3237x; 1.3338x over previous
#include <cuda_runtime.h>
#include <cuda_fp16.h>
#include <math.h>
#include <stdint.h>

// ---------------- problem constants ----------------
#define NB   128
#define LT   256
#define FH   768
#define GG   3072
#define BG   (NB*LT)

// ---- big hoisted GEMM (1-term fp16, K=768) ----
#define KH   FH              // 768
#define BK   32
#define NKH  (KH/BK)         // 24
#define ROWB 80
#define ATILE (128*ROWB)
#define STAGEB (2*ATILE)     // 20480
#define GNST 8

// ---- persistent recurrent role (2-term h, 64x64 tiles) ----
#define KR2   1536           // h packed [hh|hl]
#define RBK   64
#define RNCH  24             // 24 A chunks (12 hh + 12 hl)
#define NWCH  12             // 12 W chunks
#define RROW  144
#define RA_BY (64*RROW)      // 9216 per A stage (64 rows)
#define RNST  8
#define WCHB  (64*RROW)      // 9216 per W chunk (64 gate rows)
#define WBASE (RNST*RA_BY)   // 73728
#define PSMEM (WBASE + NWCH*WCHB)   // 73728+110592 = 184320
#define NRB   96
#define NGB   52
#define NTILE (24*LT)
#define MEGA_SMEM PSMEM      // >= GNST*STAGEB (163840)

// ---------------- scratch (device globals) ----------------
__device__ __half g_Xp [(size_t)BG * KH];     // GAT out, fp16 (1-term)
__device__ __half g_Wp [(size_t)GG * KH];     // W_ih fp16
__device__ __half g_Whp[(size_t)GG * FH];     // permuted W_hh fp16
__device__ __half g_hp [2][(size_t)NB * KR2]; // ping-pong packed h [hh|hl]
__device__ float  g_XW [(size_t)BG * GG];
__device__ unsigned g_ctr;
__device__ int      g_flag[LT];

__constant__ int c_par[24] = {-1,0,0,0,1,2,3,4,5,6,7,8,9,9,9,12,13,14,16,17,18,19,20,21};

__device__ __forceinline__ float sigm(float x) { return 1.f / (1.f + expf(-x)); }

__device__ __forceinline__ uint32_t smem_u32(const void* p) {
    uint32_t a;
    asm("{ .reg .u64 t; cvta.to.shared.u64 t, %1; cvt.u32.u64 %0, t; }" : "=r"(a) : "l"(p));
    return a;
}

__device__ __forceinline__ void cp16(uint32_t s, const void* g) {
    asm volatile("cp.async.cg.shared.global [%0], [%1], 16;" :: "r"(s), "l"(g));
}

__device__ __forceinline__ void ldm_x4(uint32_t &r0, uint32_t &r1, uint32_t &r2,
                                       uint32_t &r3, uint32_t addr) {
    asm volatile("ldmatrix.sync.aligned.m8n8.x4.shared.b16 {%0,%1,%2,%3}, [%4];"
                 : "=r"(r0), "=r"(r1), "=r"(r2), "=r"(r3) : "r"(addr));
}

__device__ __forceinline__ void mma_f16(float* d, const uint32_t* a,
                                        const uint32_t* b) {
    asm volatile(
        "mma.sync.aligned.m16n8k16.row.col.f32.f16.f16.f32 "
        "{%0,%1,%2,%3}, {%4,%5,%6,%7}, {%8,%9}, {%0,%1,%2,%3};"
        : "+f"(d[0]), "+f"(d[1]), "+f"(d[2]), "+f"(d[3])
        : "r"(a[0]), "r"(a[1]), "r"(a[2]), "r"(a[3]), "r"(b[0]), "r"(b[1]));
}

// ---------------- small prep kernels ----------------
__global__ void reset_flags() {
    int i = threadIdx.x;
    if (i == 0) g_ctr = 0u;
    if (i < LT) g_flag[i] = 0;
}

__global__ void pack_w(const float* __restrict__ W, __half* __restrict__ Wp) {
    int i = blockIdx.x * 256 + threadIdx.x;
    if (i >= GG * FH) return;
    Wp[i] = __float2half(W[i]);
}

// Block nb owns gate rows r = g*16 + fi <-> W_hh row (g*768 + nb*16 + fi).
// Layout: g_Whp[(nb*64 + r)*FH + k]
__global__ void pack_whh(const float* __restrict__ W) {
    size_t idx = (size_t)blockIdx.x * 256 + threadIdx.x;
    if (idx >= (size_t)GG * FH) return;
    int k   = (int)(idx % FH);
    int row = (int)(idx / FH);       // nb*64 + r
    int nb = row >> 6, r = row & 63;
    int g = r >> 4, fi = r & 15;
    g_Whp[idx] = __float2half(W[(size_t)(g * FH + nb * 16 + fi) * FH + k]);
}

// ---------------- GAT: one warp per graph, writes fp16 X ----------------
__global__ __launch_bounds__(256) void gat_kernel(
    const float* __restrict__ src,
    const float* __restrict__ W_pre, const float* __restrict__ b_pre,
    const float* __restrict__ W_gat,
    const float* __restrict__ att_src, const float* __restrict__ att_dst,
    const float* __restrict__ b_gat,
    __half* __restrict__ Xp)
{
    __shared__ float Wg[32 * 32];
    __shared__ float xbuf[8][24][32];
    __shared__ float asd[8][24][2];

    int tid = threadIdx.x;
    for (int i = tid; i < 1024; i += 256) Wg[i] = W_gat[i];
    __syncthreads();

    int w = tid >> 5, h = tid & 31;
    int b = blockIdx.x * 8 + w;
    int n = b >> 8, l = b & 255;

    const float* s = src + (size_t)b * 72;
    float w0 = W_pre[h], w1 = W_pre[32 + h], w2 = W_pre[64 + h], bp = b_pre[h];

    #pragma unroll
    for (int j = 0; j < 24; j++) {
        float v = fmaf(s[j*3+2], w2, fmaf(s[j*3+1], w1, fmaf(s[j*3+0], w0, bp)));
        xbuf[w][j][h] = tanhf(v);
    }
    __syncwarp();

    float asrc = att_src[h], adst = att_dst[h];
    #pragma unroll
    for (int j = 0; j < 24; j++) {
        float acc = 0.f;
        #pragma unroll
        for (int k = 0; k < 32; k++) acc = fmaf(xbuf[w][j][k], Wg[k*32 + h], acc);
        float ps = acc * asrc, pd = acc * adst;
        #pragma unroll
        for (int o = 16; o > 0; o >>= 1) {
            ps += __shfl_xor_sync(0xffffffffu, ps, o);
            pd += __shfl_xor_sync(0xffffffffu, pd, o);
        }
        __syncwarp();
        xbuf[w][j][h] = acc;
        if (h == 0) { asd[w][j][0] = ps; asd[w][j][1] = pd; }
    }
    __syncwarp();

    float bg = b_gat[h];
    size_t rbase = (size_t)(l * 128 + n) * KH;
    #pragma unroll
    for (int j = 0; j < 24; j++) {
        int p = c_par[j];
        float g;
        if (p < 0) {
            g = xbuf[w][j][h];
        } else {
            float ad = asd[w][j][1];
            float es = ad + asd[w][j][0];
            float ep = ad + asd[w][p][0];
            es = es > 0.f ? es : 0.2f * es;
            ep = ep > 0.f ? ep : 0.2f * ep;
            float m  = fmaxf(es, ep);
            float ws = expf(es - m), wp = expf(ep - m);
            float inv = 1.f / (ws + wp);
            g = (ws * xbuf[w][j][h] + wp * xbuf[w][p][h]) * inv;
        }
        Xp[rbase + j * 32 + h] = __float2half(g + bg);
    }
}

// ---------------- mega kernel ----------------
__global__ __launch_bounds__(256, 1) void mega(
    const float* __restrict__ bih, const float* __restrict__ bhh,
    float* __restrict__ out)
{
    extern __shared__ __align__(16) char sm[];
    const uint32_t smb = smem_u32(sm);

    const int tid  = threadIdx.x;
    const int lane = tid & 31;
    const int warp = tid >> 5;

    if (blockIdx.x >= NRB) {
        // ================= producer role: 1-term fp16 GEMM =================
        const int gb = blockIdx.x - NRB;
        const __half* Ap = g_Xp;
        const __half* Bp = g_Wp;
        float* C = g_XW;

        const int wm = warp >> 2;
        const int wn = warp & 3;
        const int ldRow = tid >> 2;
        const int ldSeg = tid & 3;
        const uint32_t stRow = ldRow * ROWB + ldSeg * 16;
        const uint32_t aOff = (uint32_t)((wm * 64 + (lane & 7) + ((lane >> 3) & 1) * 8) * ROWB
                                         + ((lane >> 4) & 1) * 16);
        const uint32_t bOff = (uint32_t)(ATILE + (wn * 32 + (lane & 7) + ((lane >> 4) & 1) * 8) * ROWB
                                         + ((lane >> 3) & 1) * 16);

        for (int tile = gb; tile < NTILE; tile += NGB) {
            const int y = tile / 24;
            const int x = tile % 24;
            const int m0 = y * 128;
            const int n0 = x * 128;

            const __half* gA = Ap + (size_t)(m0 + ldRow) * KH + ldSeg * 8;
            const __half* gB = Bp + (size_t)(n0 + ldRow) * KH + ldSeg * 8;

            float acc[4][4][4];
            #pragma unroll
            for (int i = 0; i < 4; i++)
                #pragma unroll
                for (int j = 0; j < 4; j++)
                    #pragma unroll
                    for (int q = 0; q < 4; q++) acc[i][j][q] = 0.f;

            #pragma unroll
            for (int pc = 0; pc < GNST - 1; pc++) {
                uint32_t sb = smb + pc * STAGEB;
                int ko = pc * BK;
                #pragma unroll
                for (int i = 0; i < 2; i++) {
                    cp16(sb + stRow + i * 64 * ROWB,         gA + (size_t)i * 64 * KH + ko);
                    cp16(sb + ATILE + stRow + i * 64 * ROWB, gB + (size_t)i * 64 * KH + ko);
                }
                asm volatile("cp.async.commit_group;");
            }

            for (int kc = 0; kc < NKH; kc++) {
                asm volatile("cp.async.wait_group %0;" :: "n"(GNST - 2));
                __syncthreads();

                if (kc + GNST - 1 < NKH) {
                    uint32_t sb = smb + ((kc + GNST - 1) & (GNST - 1)) * STAGEB;
                    int ko = (kc + GNST - 1) * BK;
                    #pragma unroll
                    for (int i = 0; i < 2; i++) {
                        cp16(sb + stRow + i * 64 * ROWB,         gA + (size_t)i * 64 * KH + ko);
                        cp16(sb + ATILE + stRow + i * 64 * ROWB, gB + (size_t)i * 64 * KH + ko);
                    }
                }
                asm volatile("cp.async.commit_group;");

                const uint32_t soff = smb + (kc & (GNST - 1)) * STAGEB;
                #pragma unroll
                for (int ks = 0; ks < 2; ks++) {
                    uint32_t a[4][4], bq[4][2];
                    #pragma unroll
                    for (int tm = 0; tm < 4; tm++)
                        ldm_x4(a[tm][0], a[tm][1], a[tm][2], a[tm][3],
                               soff + aOff + tm * (16 * ROWB) + ks * 32);
                    #pragma unroll
                    for (int tb = 0; tb < 2; tb++) {
                        uint32_t r0, r1, r2, r3;
                        ldm_x4(r0, r1, r2, r3, soff + bOff + tb * (16 * ROWB) + ks * 32);
                        bq[2*tb][0] = r0; bq[2*tb][1] = r1;
                        bq[2*tb+1][0] = r2; bq[2*tb+1][1] = r3;
                    }
                    #pragma unroll
                    for (int tm = 0; tm < 4; tm++)
                        #pragma unroll
                        for (int tn = 0; tn < 4; tn++)
                            mma_f16(acc[tm][tn], a[tm], bq[tn]);
                }
            }
            asm volatile("cp.async.wait_group 0;");

            #pragma unroll
            for (int tm = 0; tm < 4; tm++) {
                int row = m0 + wm * 64 + tm * 16 + (lane >> 2);
                #pragma unroll
                for (int tn = 0; tn < 4; tn++) {
                    int col = n0 + wn * 32 + tn * 8 + (lane & 3) * 2;
                    float* p = C + (size_t)row * GG + col;
                    *(float2*)p                    = make_float2(acc[tm][tn][0], acc[tm][tn][1]);
                    *(float2*)(p + (size_t)8 * GG) = make_float2(acc[tm][tn][2], acc[tm][tn][3]);
                }
            }

            __threadfence();
            __syncthreads();
            if (tid == 0) atomicAdd(&g_flag[y], 1);
            __syncthreads();
        }
        return;
    }

    // ================= consumer role: persistent LSTM, 64x64 tiles =================
    const int b  = blockIdx.x;
    const int mb = b & 1;            // m half
    const int nb = b >> 1;           // n slice (64 gate rows = 16 features)
    const int m0 = mb * 64;

    const int wm = warp >> 2;        // 0..1: 32-row m strip
    const int wn = warp & 3;         // 0..3: 16-row n strip

    const int efi = tid & 15;        // feature within slice
    const int em0 = tid >> 4;        // base local m (0..15)
    const int feat = nb * 16 + efi;

    // one-time resident W slice (12 chunks x 64 rows x 64 halfs)
    {
        const __half* Wb = g_Whp + (size_t)nb * 64 * FH;
        for (int i = tid; i < NWCH * 512; i += 256) {
            int chunk = i >> 9;
            int rem   = i & 511;
            int row   = rem >> 3, seg = rem & 7;
            cp16(smb + WBASE + chunk * WCHB + row * RROW + seg * 16,
                 Wb + (size_t)row * FH + chunk * RBK + seg * 8);
        }
        asm volatile("cp.async.commit_group;");
        asm volatile("cp.async.wait_group 0;");
    }

    float bias_r[4];
    #pragma unroll
    for (int g = 0; g < 4; g++) bias_r[g] = bih[g * FH + feat] + bhh[g * FH + feat];

    float creg[4] = {0.f, 0.f, 0.f, 0.f};

    __syncthreads();

    const uint32_t aOff = (uint32_t)((wm * 32 + (lane & 15)) * RROW
                                     + ((lane >> 4) & 1) * 16);
    const uint32_t bOffW = (uint32_t)((wn * 16 + (lane & 7) + ((lane >> 4) & 1) * 8) * RROW
                                      + ((lane >> 3) & 1) * 16);

    unsigned* ctr = &g_ctr;
    const float* xwbase = g_XW;

    for (int t = 0; t < LT; t++) {
        const __half* hin   = g_hp[(t + 1) & 1];
        __half*       houtp = g_hp[t & 1];
        const float*  xw    = xwbase + (size_t)t * NB * GG;

        if (tid == 0) {
            while (*(volatile int*)&g_flag[t] < 24) { __nanosleep(128); }
            __threadfence();
        }
        __syncthreads();

        float xwv[4][4];
        #pragma unroll
        for (int i = 0; i < 4; i++) {
            const float* xwr = xw + (size_t)(m0 + em0 + i * 16) * GG + feat;
            xwv[i][0] = xwr[0];
            xwv[i][1] = xwr[FH];
            xwv[i][2] = xwr[2 * FH];
            xwv[i][3] = xwr[3 * FH];
        }

        float acc[2][2][4];
        #pragma unroll
        for (int i = 0; i < 2; i++)
            #pragma unroll
            for (int j = 0; j < 2; j++)
                #pragma unroll
                for (int q = 0; q < 4; q++) acc[i][j][q] = 0.f;

        if (t > 0) {
            #pragma unroll
            for (int pc = 0; pc < RNST - 1; pc++) {
                uint32_t sb = smb + pc * RA_BY;
                int ko = pc * RBK;
                #pragma unroll
                for (int i = 0; i < 2; i++) {
                    int slot = tid + i * 256;
                    int row = slot >> 3, seg = slot & 7;
                    cp16(sb + row * RROW + seg * 16,
                         hin + (size_t)(m0 + row) * KR2 + ko + seg * 8);
                }
                asm volatile("cp.async.commit_group;");
            }

            int stage = 0, pstage = RNST - 1;
            for (int kc = 0; kc < RNCH; kc++) {
                asm volatile("cp.async.wait_group %0;" :: "n"(RNST - 2));
                __syncthreads();

                if (kc + RNST - 1 < RNCH) {
                    int nc = kc + RNST - 1;
                    uint32_t sb = smb + pstage * RA_BY;
                    int ko = nc * RBK;
                    #pragma unroll
                    for (int i = 0; i < 2; i++) {
                        int slot = tid + i * 256;
                        int row = slot >> 3, seg = slot & 7;
                        cp16(sb + row * RROW + seg * 16,
                             hin + (size_t)(m0 + row) * KR2 + ko + seg * 8);
                    }
                }
                asm volatile("cp.async.commit_group;");

                const uint32_t soff = smb + stage * RA_BY;
                const uint32_t woff = smb + WBASE + ((kc < NWCH) ? kc : kc - NWCH) * WCHB;

                #pragma unroll
                for (int ks = 0; ks < RBK / 16; ks++) {
                    uint32_t a[2][4], bq[2][2];
                    #pragma unroll
                    for (int tm = 0; tm < 2; tm++)
                        ldm_x4(a[tm][0], a[tm][1], a[tm][2], a[tm][3],
                               soff + aOff + tm * (16 * RROW) + ks * 32);
                    {
                        uint32_t r0, r1, r2, r3;
                        ldm_x4(r0, r1, r2, r3, woff + bOffW + ks * 32);
                        bq[0][0] = r0; bq[0][1] = r1;
                        bq[1][0] = r2; bq[1][1] = r3;
                    }
                    #pragma unroll
                    for (int tm = 0; tm < 2; tm++)
                        #pragma unroll
                        for (int tn = 0; tn < 2; tn++)
                            mma_f16(acc[tm][tn], a[tm], bq[tn]);
                }

                if (++stage == RNST) stage = 0;
                if (++pstage == RNST) pstage = 0;
            }
            asm volatile("cp.async.wait_group 0;");
        }
        __syncthreads();

        // gate tile: Gt[64 n][65 m] fp32 (aliases A-stage smem)
        float* Gt = (float*)sm;
        #pragma unroll
        for (int tm = 0; tm < 2; tm++) {
            int m = wm * 32 + tm * 16 + (lane >> 2);
            #pragma unroll
            for (int tn = 0; tn < 2; tn++) {
                int n = wn * 16 + tn * 8 + (lane & 3) * 2;
                Gt[n * 65 + m]           = acc[tm][tn][0];
                Gt[(n + 1) * 65 + m]     = acc[tm][tn][1];
                Gt[n * 65 + m + 8]       = acc[tm][tn][2];
                Gt[(n + 1) * 65 + m + 8] = acc[tm][tn][3];
            }
        }
        __syncthreads();

        // pointwise: 16 feat x 64 m, 4 cells/thread; publish h, arrive, then out
        float hvv[4];
        #pragma unroll
        for (int i = 0; i < 4; i++) {
            int ml = em0 + i * 16;          // local m
            int m  = m0 + ml;               // global m

            float gi = Gt[(0*16 + efi) * 65 + ml] + xwv[i][0] + bias_r[0];
            float gf = Gt[(1*16 + efi) * 65 + ml] + xwv[i][1] + bias_r[1];
            float gg = Gt[(2*16 + efi) * 65 + ml] + xwv[i][2] + bias_r[2];
            float go = Gt[(3*16 + efi) * 65 + ml] + xwv[i][3] + bias_r[3];

            float c  = sigm(gf) * creg[i] + sigm(gi) * tanhf(gg);
            float hv = sigm(go) * tanhf(c);
            creg[i] = c;
            hvv[i] = hv;

            __half hh = __float2half(hv);
            size_t hb = (size_t)m * KR2 + feat;
            houtp[hb]      = hh;
            houtp[hb + FH] = __float2half(hv - __half2float(hh));
        }

        __threadfence();
        __syncthreads();
        if (tid == 0) atomicAdd(ctr, 1u);

        #pragma unroll
        for (int i = 0; i < 4; i++) {
            int m = m0 + em0 + i * 16;
            out[((size_t)m * LT + t) * FH + feat] = hvv[i];
            if (t == LT - 1) {
                out[(size_t)NB * LT * FH + (size_t)m * FH + feat]           = hvv[i];
                out[(size_t)NB * LT * FH + NB * FH + (size_t)m * FH + feat] = creg[i];
            }
        }

        if (tid == 0) {
            unsigned target = (unsigned)NRB * (unsigned)(t + 1);
            while (*(volatile unsigned*)ctr < target) { __nanosleep(64); }
            __threadfence();
        }
        __syncthreads();
    }
}

// ---------------- launch ----------------
extern "C" void kernel_launch(void* const* d_in, const int* in_sizes, int n_in,
                              void* d_out, int out_size)
{
    const float* src     = (const float*)d_in[0];
    const float* W_pre   = (const float*)d_in[1];
    const float* b_pre   = (const float*)d_in[2];
    const float* W_gat   = (const float*)d_in[3];
    const float* att_src = (const float*)d_in[4];
    const float* att_dst = (const float*)d_in[5];
    const float* b_gat   = (const float*)d_in[6];
    const float* W_ih    = (const float*)d_in[7];
    const float* W_hh    = (const float*)d_in[8];
    const float* b_ih    = (const float*)d_in[9];
    const float* b_hh    = (const float*)d_in[10];
    float* out = (float*)d_out;

    __half *Xp, *Wp;
    cudaGetSymbolAddress((void**)&Xp,  g_Xp);
    cudaGetSymbolAddress((void**)&Wp,  g_Wp);

    cudaFuncSetAttribute(mega, cudaFuncAttributeMaxDynamicSharedMemorySize,
                         MEGA_SMEM);

    // 0) prep
    reset_flags<<<1, 256>>>();
    pack_w<<<(GG * FH + 255) / 256, 256>>>(W_ih, Wp);
    pack_whh<<<(unsigned)(((size_t)GG * FH + 255) / 256), 256>>>(W_hh);

    // 1) GAT -> fp16 X
    gat_kernel<<<BG / 8, 256>>>(src, W_pre, b_pre, W_gat, att_src, att_dst, b_gat, Xp);

    // 2) fused producer-GEMM + persistent-LSTM
    mega<<<NRB + NGB, 256, MEGA_SMEM>>>(b_ih, b_hh, out);
}

// round 13
// speedup vs baseline: 3.1883x; 1.3721x over previous
#include <cuda_runtime.h>
#include <cuda_fp16.h>
#include <math.h>
#include <stdint.h>

// ---------------- problem constants ----------------
#define NB   128
#define LT   256
#define FH   768
#define GG   3072
#define BG   (NB*LT)

// ---- big hoisted GEMM (1-term fp16, K=768) ----
#define KH   FH              // 768
#define BK   32
#define NKH  (KH/BK)         // 24
#define ROWB 80
#define ATILE (128*ROWB)
#define STAGEB (2*ATILE)     // 20480
#define GNST 8

// ---- persistent recurrent role (1-term fp16 h, 64x64 tiles) ----
#define RBK   64
#define RNCH  12             // 12 A chunks (K=768)
#define NWCH  12             // 12 W chunks (1:1 with A chunks)
#define RROW  144
#define RA_BY (64*RROW)      // 9216 per A stage
#define RNST  8
#define WCHB  (64*RROW)      // 9216 per W chunk
#define WBASE (RNST*RA_BY)   // 73728
#define PSMEM (WBASE + NWCH*WCHB)   // 184320
#define NRB   96
#define NGB   52
#define NTILE (24*LT)
#define MEGA_SMEM PSMEM      // >= GNST*STAGEB (163840)

// ---------------- scratch (device globals) ----------------
__device__ __half g_Xp [(size_t)BG * KH];     // GAT out, fp16
__device__ __half g_Wp [(size_t)GG * KH];     // W_ih fp16
__device__ __half g_Whp[(size_t)GG * FH];     // permuted W_hh fp16
__device__ __half g_hp [2][(size_t)NB * FH];  // ping-pong h, fp16
__device__ float  g_XW [(size_t)BG * GG];
__device__ unsigned g_ctr2[2][32];            // per-m-half barrier counters (padded)
__device__ int      g_flag[LT];

__constant__ int c_par[24] = {-1,0,0,0,1,2,3,4,5,6,7,8,9,9,9,12,13,14,16,17,18,19,20,21};

__device__ __forceinline__ float sigm(float x) { return 1.f / (1.f + expf(-x)); }

__device__ __forceinline__ uint32_t smem_u32(const void* p) {
    uint32_t a;
    asm("{ .reg .u64 t; cvta.to.shared.u64 t, %1; cvt.u32.u64 %0, t; }" : "=r"(a) : "l"(p));
    return a;
}

__device__ __forceinline__ void cp16(uint32_t s, const void* g) {
    asm volatile("cp.async.cg.shared.global [%0], [%1], 16;" :: "r"(s), "l"(g));
}

__device__ __forceinline__ void ldm_x4(uint32_t &r0, uint32_t &r1, uint32_t &r2,
                                       uint32_t &r3, uint32_t addr) {
    asm volatile("ldmatrix.sync.aligned.m8n8.x4.shared.b16 {%0,%1,%2,%3}, [%4];"
                 : "=r"(r0), "=r"(r1), "=r"(r2), "=r"(r3) : "r"(addr));
}

__device__ __forceinline__ void mma_f16(float* d, const uint32_t* a,
                                        const uint32_t* b) {
    asm volatile(
        "mma.sync.aligned.m16n8k16.row.col.f32.f16.f16.f32 "
        "{%0,%1,%2,%3}, {%4,%5,%6,%7}, {%8,%9}, {%0,%1,%2,%3};"
        : "+f"(d[0]), "+f"(d[1]), "+f"(d[2]), "+f"(d[3])
        : "r"(a[0]), "r"(a[1]), "r"(a[2]), "r"(a[3]), "r"(b[0]), "r"(b[1]));
}

// ---------------- small prep kernels ----------------
__global__ void reset_flags() {
    int i = threadIdx.x;
    if (i < 64) ((unsigned*)g_ctr2)[i] = 0u;
    if (i < LT) g_flag[i] = 0;
}

__global__ void pack_w(const float* __restrict__ W, __half* __restrict__ Wp) {
    int i = blockIdx.x * 256 + threadIdx.x;
    if (i >= GG * FH) return;
    Wp[i] = __float2half(W[i]);
}

// Block nb owns gate rows r = g*16 + fi <-> W_hh row (g*768 + nb*16 + fi).
__global__ void pack_whh(const float* __restrict__ W) {
    size_t idx = (size_t)blockIdx.x * 256 + threadIdx.x;
    if (idx >= (size_t)GG * FH) return;
    int k   = (int)(idx % FH);
    int row = (int)(idx / FH);       // nb*64 + r
    int nb = row >> 6, r = row & 63;
    int g = r >> 4, fi = r & 15;
    g_Whp[idx] = __float2half(W[(size_t)(g * FH + nb * 16 + fi) * FH + k]);
}

// ---------------- GAT: one warp per graph, writes fp16 X ----------------
__global__ __launch_bounds__(256) void gat_kernel(
    const float* __restrict__ src,
    const float* __restrict__ W_pre, const float* __restrict__ b_pre,
    const float* __restrict__ W_gat,
    const float* __restrict__ att_src, const float* __restrict__ att_dst,
    const float* __restrict__ b_gat,
    __half* __restrict__ Xp)
{
    __shared__ float Wg[32 * 32];
    __shared__ float xbuf[8][24][32];
    __shared__ float asd[8][24][2];

    int tid = threadIdx.x;
    for (int i = tid; i < 1024; i += 256) Wg[i] = W_gat[i];
    __syncthreads();

    int w = tid >> 5, h = tid & 31;
    int b = blockIdx.x * 8 + w;
    int n = b >> 8, l = b & 255;

    const float* s = src + (size_t)b * 72;
    float w0 = W_pre[h], w1 = W_pre[32 + h], w2 = W_pre[64 + h], bp = b_pre[h];

    #pragma unroll
    for (int j = 0; j < 24; j++) {
        float v = fmaf(s[j*3+2], w2, fmaf(s[j*3+1], w1, fmaf(s[j*3+0], w0, bp)));
        xbuf[w][j][h] = tanhf(v);
    }
    __syncwarp();

    float asrc = att_src[h], adst = att_dst[h];
    #pragma unroll
    for (int j = 0; j < 24; j++) {
        float acc = 0.f;
        #pragma unroll
        for (int k = 0; k < 32; k++) acc = fmaf(xbuf[w][j][k], Wg[k*32 + h], acc);
        float ps = acc * asrc, pd = acc * adst;
        #pragma unroll
        for (int o = 16; o > 0; o >>= 1) {
            ps += __shfl_xor_sync(0xffffffffu, ps, o);
            pd += __shfl_xor_sync(0xffffffffu, pd, o);
        }
        __syncwarp();
        xbuf[w][j][h] = acc;
        if (h == 0) { asd[w][j][0] = ps; asd[w][j][1] = pd; }
    }
    __syncwarp();

    float bg = b_gat[h];
    size_t rbase = (size_t)(l * 128 + n) * KH;
    #pragma unroll
    for (int j = 0; j < 24; j++) {
        int p = c_par[j];
        float g;
        if (p < 0) {
            g = xbuf[w][j][h];
        } else {
            float ad = asd[w][j][1];
            float es = ad + asd[w][j][0];
            float ep = ad + asd[w][p][0];
            es = es > 0.f ? es : 0.2f * es;
            ep = ep > 0.f ? ep : 0.2f * ep;
            float m  = fmaxf(es, ep);
            float ws = expf(es - m), wp = expf(ep - m);
            float inv = 1.f / (ws + wp);
            g = (ws * xbuf[w][j][h] + wp * xbuf[w][p][h]) * inv;
        }
        Xp[rbase + j * 32 + h] = __float2half(g + bg);
    }
}

// ---------------- mega kernel ----------------
__global__ __launch_bounds__(256, 1) void mega(
    const float* __restrict__ bih, const float* __restrict__ bhh,
    float* __restrict__ out)
{
    extern __shared__ __align__(16) char sm[];
    const uint32_t smb = smem_u32(sm);

    const int tid  = threadIdx.x;
    const int lane = tid & 31;
    const int warp = tid >> 5;

    if (blockIdx.x >= NRB) {
        // ================= producer role: 1-term fp16 GEMM =================
        const int gb = blockIdx.x - NRB;
        const __half* Ap = g_Xp;
        const __half* Bp = g_Wp;
        float* C = g_XW;

        const int wm = warp >> 2;
        const int wn = warp & 3;
        const int ldRow = tid >> 2;
        const int ldSeg = tid & 3;
        const uint32_t stRow = ldRow * ROWB + ldSeg * 16;
        const uint32_t aOff = (uint32_t)((wm * 64 + (lane & 7) + ((lane >> 3) & 1) * 8) * ROWB
                                         + ((lane >> 4) & 1) * 16);
        const uint32_t bOff = (uint32_t)(ATILE + (wn * 32 + (lane & 7) + ((lane >> 4) & 1) * 8) * ROWB
                                         + ((lane >> 3) & 1) * 16);

        for (int tile = gb; tile < NTILE; tile += NGB) {
            const int y = tile / 24;
            const int x = tile % 24;
            const int m0 = y * 128;
            const int n0 = x * 128;

            const __half* gA = Ap + (size_t)(m0 + ldRow) * KH + ldSeg * 8;
            const __half* gB = Bp + (size_t)(n0 + ldRow) * KH + ldSeg * 8;

            float acc[4][4][4];
            #pragma unroll
            for (int i = 0; i < 4; i++)
                #pragma unroll
                for (int j = 0; j < 4; j++)
                    #pragma unroll
                    for (int q = 0; q < 4; q++) acc[i][j][q] = 0.f;

            #pragma unroll
            for (int pc = 0; pc < GNST - 1; pc++) {
                uint32_t sb = smb + pc * STAGEB;
                int ko = pc * BK;
                #pragma unroll
                for (int i = 0; i < 2; i++) {
                    cp16(sb + stRow + i * 64 * ROWB,         gA + (size_t)i * 64 * KH + ko);
                    cp16(sb + ATILE + stRow + i * 64 * ROWB, gB + (size_t)i * 64 * KH + ko);
                }
                asm volatile("cp.async.commit_group;");
            }

            for (int kc = 0; kc < NKH; kc++) {
                asm volatile("cp.async.wait_group %0;" :: "n"(GNST - 2));
                __syncthreads();

                if (kc + GNST - 1 < NKH) {
                    uint32_t sb = smb + ((kc + GNST - 1) & (GNST - 1)) * STAGEB;
                    int ko = (kc + GNST - 1) * BK;
                    #pragma unroll
                    for (int i = 0; i < 2; i++) {
                        cp16(sb + stRow + i * 64 * ROWB,         gA + (size_t)i * 64 * KH + ko);
                        cp16(sb + ATILE + stRow + i * 64 * ROWB, gB + (size_t)i * 64 * KH + ko);
                    }
                }
                asm volatile("cp.async.commit_group;");

                const uint32_t soff = smb + (kc & (GNST - 1)) * STAGEB;
                #pragma unroll
                for (int ks = 0; ks < 2; ks++) {
                    uint32_t a[4][4], bq[4][2];
                    #pragma unroll
                    for (int tm = 0; tm < 4; tm++)
                        ldm_x4(a[tm][0], a[tm][1], a[tm][2], a[tm][3],
                               soff + aOff + tm * (16 * ROWB) + ks * 32);
                    #pragma unroll
                    for (int tb = 0; tb < 2; tb++) {
                        uint32_t r0, r1, r2, r3;
                        ldm_x4(r0, r1, r2, r3, soff + bOff + tb * (16 * ROWB) + ks * 32);
                        bq[2*tb][0] = r0; bq[2*tb][1] = r1;
                        bq[2*tb+1][0] = r2; bq[2*tb+1][1] = r3;
                    }
                    #pragma unroll
                    for (int tm = 0; tm < 4; tm++)
                        #pragma unroll
                        for (int tn = 0; tn < 4; tn++)
                            mma_f16(acc[tm][tn], a[tm], bq[tn]);
                }
            }
            asm volatile("cp.async.wait_group 0;");

            #pragma unroll
            for (int tm = 0; tm < 4; tm++) {
                int row = m0 + wm * 64 + tm * 16 + (lane >> 2);
                #pragma unroll
                for (int tn = 0; tn < 4; tn++) {
                    int col = n0 + wn * 32 + tn * 8 + (lane & 3) * 2;
                    float* p = C + (size_t)row * GG + col;
                    *(float2*)p                    = make_float2(acc[tm][tn][0], acc[tm][tn][1]);
                    *(float2*)(p + (size_t)8 * GG) = make_float2(acc[tm][tn][2], acc[tm][tn][3]);
                }
            }

            __threadfence();
            __syncthreads();
            if (tid == 0) atomicAdd(&g_flag[y], 1);
            __syncthreads();
        }
        return;
    }

    // ================= consumer role: persistent LSTM (1-term, 64x64) ==========
    const int b  = blockIdx.x;
    const int mb = b & 1;            // m half
    const int nb = b >> 1;           // n slice (64 gate rows = 16 features)
    const int m0 = mb * 64;

    const int wm = warp >> 2;        // 0..1: 32-row m strip
    const int wn = warp & 3;         // 0..3: 16-row n strip

    const int efi = tid & 15;
    const int em0 = tid >> 4;        // 0..15
    const int feat = nb * 16 + efi;

    // one-time resident W slice (12 chunks x 64 rows x 64 halfs)
    {
        const __half* Wb = g_Whp + (size_t)nb * 64 * FH;
        for (int i = tid; i < NWCH * 512; i += 256) {
            int chunk = i >> 9;
            int rem   = i & 511;
            int row   = rem >> 3, seg = rem & 7;
            cp16(smb + WBASE + chunk * WCHB + row * RROW + seg * 16,
                 Wb + (size_t)row * FH + chunk * RBK + seg * 8);
        }
        asm volatile("cp.async.commit_group;");
        asm volatile("cp.async.wait_group 0;");
    }

    float bias_r[4];
    #pragma unroll
    for (int g = 0; g < 4; g++) bias_r[g] = bih[g * FH + feat] + bhh[g * FH + feat];

    float creg[4] = {0.f, 0.f, 0.f, 0.f};

    __syncthreads();

    const uint32_t aOff = (uint32_t)((wm * 32 + (lane & 15)) * RROW
                                     + ((lane >> 4) & 1) * 16);
    const uint32_t bOffW = (uint32_t)((wn * 16 + (lane & 7) + ((lane >> 4) & 1) * 8) * RROW
                                      + ((lane >> 3) & 1) * 16);

    unsigned* ctr = &g_ctr2[mb][0];
    const float* xwbase = g_XW;

    for (int t = 0; t < LT; t++) {
        const __half* hin   = g_hp[(t + 1) & 1];
        __half*       houtp = g_hp[t & 1];
        const float*  xw    = xwbase + (size_t)t * NB * GG;

        if (tid == 0) {
            while (*(volatile int*)&g_flag[t] < 24) { __nanosleep(128); }
            __threadfence();
        }
        __syncthreads();

        float xwv[4][4];
        #pragma unroll
        for (int i = 0; i < 4; i++) {
            const float* xwr = xw + (size_t)(m0 + em0 + i * 16) * GG + feat;
            xwv[i][0] = xwr[0];
            xwv[i][1] = xwr[FH];
            xwv[i][2] = xwr[2 * FH];
            xwv[i][3] = xwr[3 * FH];
        }

        float acc[2][2][4];
        #pragma unroll
        for (int i = 0; i < 2; i++)
            #pragma unroll
            for (int j = 0; j < 2; j++)
                #pragma unroll
                for (int q = 0; q < 4; q++) acc[i][j][q] = 0.f;

        if (t > 0) {
            #pragma unroll
            for (int pc = 0; pc < RNST - 1; pc++) {
                if (pc < RNCH) {
                    uint32_t sb = smb + pc * RA_BY;
                    int ko = pc * RBK;
                    #pragma unroll
                    for (int i = 0; i < 2; i++) {
                        int slot = tid + i * 256;
                        int row = slot >> 3, seg = slot & 7;
                        cp16(sb + row * RROW + seg * 16,
                             hin + (size_t)(m0 + row) * FH + ko + seg * 8);
                    }
                }
                asm volatile("cp.async.commit_group;");
            }

            int stage = 0, pstage = RNST - 1;
            for (int kc = 0; kc < RNCH; kc++) {
                asm volatile("cp.async.wait_group %0;" :: "n"(RNST - 2));
                __syncthreads();

                if (kc + RNST - 1 < RNCH) {
                    int nc = kc + RNST - 1;
                    uint32_t sb = smb + pstage * RA_BY;
                    int ko = nc * RBK;
                    #pragma unroll
                    for (int i = 0; i < 2; i++) {
                        int slot = tid + i * 256;
                        int row = slot >> 3, seg = slot & 7;
                        cp16(sb + row * RROW + seg * 16,
                             hin + (size_t)(m0 + row) * FH + ko + seg * 8);
                    }
                }
                asm volatile("cp.async.commit_group;");

                const uint32_t soff = smb + stage * RA_BY;
                const uint32_t woff = smb + WBASE + kc * WCHB;

                #pragma unroll
                for (int ks = 0; ks < RBK / 16; ks++) {
                    uint32_t a[2][4], bq[2][2];
                    #pragma unroll
                    for (int tm = 0; tm < 2; tm++)
                        ldm_x4(a[tm][0], a[tm][1], a[tm][2], a[tm][3],
                               soff + aOff + tm * (16 * RROW) + ks * 32);
                    {
                        uint32_t r0, r1, r2, r3;
                        ldm_x4(r0, r1, r2, r3, woff + bOffW + ks * 32);
                        bq[0][0] = r0; bq[0][1] = r1;
                        bq[1][0] = r2; bq[1][1] = r3;
                    }
                    #pragma unroll
                    for (int tm = 0; tm < 2; tm++)
                        #pragma unroll
                        for (int tn = 0; tn < 2; tn++)
                            mma_f16(acc[tm][tn], a[tm], bq[tn]);
                }

                if (++stage == RNST) stage = 0;
                if (++pstage == RNST) pstage = 0;
            }
            asm volatile("cp.async.wait_group 0;");
        }
        __syncthreads();

        // gate tile: Gt[64 n][65 m] fp32 (aliases A-stage smem)
        float* Gt = (float*)sm;
        #pragma unroll
        for (int tm = 0; tm < 2; tm++) {
            int m = wm * 32 + tm * 16 + (lane >> 2);
            #pragma unroll
            for (int tn = 0; tn < 2; tn++) {
                int n = wn * 16 + tn * 8 + (lane & 3) * 2;
                Gt[n * 65 + m]           = acc[tm][tn][0];
                Gt[(n + 1) * 65 + m]     = acc[tm][tn][1];
                Gt[n * 65 + m + 8]       = acc[tm][tn][2];
                Gt[(n + 1) * 65 + m + 8] = acc[tm][tn][3];
            }
        }
        __syncthreads();

        // pointwise: 16 feat x 64 m, 4 cells/thread; publish h, arrive, then out
        float hvv[4];
        #pragma unroll
        for (int i = 0; i < 4; i++) {
            int ml = em0 + i * 16;
            int m  = m0 + ml;

            float gi = Gt[(0*16 + efi) * 65 + ml] + xwv[i][0] + bias_r[0];
            float gf = Gt[(1*16 + efi) * 65 + ml] + xwv[i][1] + bias_r[1];
            float gg = Gt[(2*16 + efi) * 65 + ml] + xwv[i][2] + bias_r[2];
            float go = Gt[(3*16 + efi) * 65 + ml] + xwv[i][3] + bias_r[3];

            float c  = sigm(gf) * creg[i] + sigm(gi) * tanhf(gg);
            float hv = sigm(go) * tanhf(c);
            creg[i] = c;
            hvv[i] = hv;

            houtp[(size_t)m * FH + feat] = __float2half(hv);
        }

        __threadfence();
        __syncthreads();
        if (tid == 0) atomicAdd(ctr, 1u);

        #pragma unroll
        for (int i = 0; i < 4; i++) {
            int m = m0 + em0 + i * 16;
            out[((size_t)m * LT + t) * FH + feat] = hvv[i];
            if (t == LT - 1) {
                out[(size_t)NB * LT * FH + (size_t)m * FH + feat]           = hvv[i];
                out[(size_t)NB * LT * FH + NB * FH + (size_t)m * FH + feat] = creg[i];
            }
        }

        // wait for the 48 same-half arrivals of step t
        if (tid == 0) {
            unsigned target = 48u * (unsigned)(t + 1);
            while (*(volatile unsigned*)ctr < target) { __nanosleep(64); }
            __threadfence();
        }
        __syncthreads();
    }
}

// ---------------- launch ----------------
extern "C" void kernel_launch(void* const* d_in, const int* in_sizes, int n_in,
                              void* d_out, int out_size)
{
    const float* src     = (const float*)d_in[0];
    const float* W_pre   = (const float*)d_in[1];
    const float* b_pre   = (const float*)d_in[2];
    const float* W_gat   = (const float*)d_in[3];
    const float* att_src = (const float*)d_in[4];
    const float* att_dst = (const float*)d_in[5];
    const float* b_gat   = (const float*)d_in[6];
    const float* W_ih    = (const float*)d_in[7];
    const float* W_hh    = (const float*)d_in[8];
    const float* b_ih    = (const float*)d_in[9];
    const float* b_hh    = (const float*)d_in[10];
    float* out = (float*)d_out;

    __half *Xp, *Wp;
    cudaGetSymbolAddress((void**)&Xp,  g_Xp);
    cudaGetSymbolAddress((void**)&Wp,  g_Wp);

    cudaFuncSetAttribute(mega, cudaFuncAttributeMaxDynamicSharedMemorySize,
                         MEGA_SMEM);

    // 0) prep
    reset_flags<<<1, 256>>>();
    pack_w<<<(GG * FH + 255) / 256, 256>>>(W_ih, Wp);
    pack_whh<<<(unsigned)(((size_t)GG * FH + 255) / 256), 256>>>(W_hh);

    // 1) GAT -> fp16 X
    gat_kernel<<<BG / 8, 256>>>(src, W_pre, b_pre, W_gat, att_src, att_dst, b_gat, Xp);

    // 2) fused producer-GEMM + persistent-LSTM
    mega<<<NRB + NGB, 256, MEGA_SMEM>>>(b_ih, b_hh, out);
}

// round 14
// speedup vs baseline: 3.2975x; 1.0342x over previous
#include <cuda_runtime.h>
#include <cuda_fp16.h>
#include <math.h>
#include <stdint.h>

// ---------------- problem constants ----------------
#define NB   128
#define LT   256
#define FH   768
#define GG   3072
#define BG   (NB*LT)

// ---- big hoisted GEMM (1-term fp16, K=768) ----
#define KH   FH              // 768
#define BK   32
#define NKH  (KH/BK)         // 24
#define ROWB 80
#define ATILE (128*ROWB)
#define STAGEB (2*ATILE)     // 20480
#define GNST 8

// ---- persistent recurrent role (1-term fp16 h, 64x64 tiles, full-resident A) ----
#define RBK   64
#define RNCH  12             // 12 A chunks (K=768)
#define NWCH  12             // 12 W chunks
#define RROW  144
#define ACHB  (64*RROW)      // 9216 per A chunk
#define ABASE 0
#define WBASE (RNCH*ACHB)    // 110592
#define WCHB  (64*RROW)      // 9216 per W chunk
#define PSMEM (WBASE + NWCH*WCHB)   // 221184
#define NRB   96
#define NGB   52
#define NTILE (24*LT)
#define MEGA_SMEM PSMEM      // >= GNST*STAGEB (163840)

// ---------------- scratch (device globals) ----------------
__device__ __half g_Xp [(size_t)BG * KH];     // GAT out, fp16
__device__ __half g_Wp [(size_t)GG * KH];     // W_ih fp16
__device__ __half g_Whp[(size_t)GG * FH];     // permuted W_hh fp16
__device__ __half g_hp [2][(size_t)NB * FH];  // ping-pong h, fp16
__device__ float  g_XW [(size_t)BG * GG];
__device__ unsigned g_ctr2[2][32];            // per-m-half barrier counters (padded)
__device__ int      g_flag[LT];

__constant__ int c_par[24] = {-1,0,0,0,1,2,3,4,5,6,7,8,9,9,9,12,13,14,16,17,18,19,20,21};

__device__ __forceinline__ float sigm(float x) { return 1.f / (1.f + expf(-x)); }

__device__ __forceinline__ uint32_t smem_u32(const void* p) {
    uint32_t a;
    asm("{ .reg .u64 t; cvta.to.shared.u64 t, %1; cvt.u32.u64 %0, t; }" : "=r"(a) : "l"(p));
    return a;
}

__device__ __forceinline__ void cp16(uint32_t s, const void* g) {
    asm volatile("cp.async.cg.shared.global [%0], [%1], 16;" :: "r"(s), "l"(g));
}

__device__ __forceinline__ void ldm_x4(uint32_t &r0, uint32_t &r1, uint32_t &r2,
                                       uint32_t &r3, uint32_t addr) {
    asm volatile("ldmatrix.sync.aligned.m8n8.x4.shared.b16 {%0,%1,%2,%3}, [%4];"
                 : "=r"(r0), "=r"(r1), "=r"(r2), "=r"(r3) : "r"(addr));
}

__device__ __forceinline__ void mma_f16(float* d, const uint32_t* a,
                                        const uint32_t* b) {
    asm volatile(
        "mma.sync.aligned.m16n8k16.row.col.f32.f16.f16.f32 "
        "{%0,%1,%2,%3}, {%4,%5,%6,%7}, {%8,%9}, {%0,%1,%2,%3};"
        : "+f"(d[0]), "+f"(d[1]), "+f"(d[2]), "+f"(d[3])
        : "r"(a[0]), "r"(a[1]), "r"(a[2]), "r"(a[3]), "r"(b[0]), "r"(b[1]));
}

// ---------------- small prep kernels ----------------
__global__ void reset_flags() {
    int i = threadIdx.x;
    if (i < 64) ((unsigned*)g_ctr2)[i] = 0u;
    if (i < LT) g_flag[i] = 0;
}

__global__ void pack_w(const float* __restrict__ W, __half* __restrict__ Wp) {
    int i = blockIdx.x * 256 + threadIdx.x;
    if (i >= GG * FH) return;
    Wp[i] = __float2half(W[i]);
}

// Block nb owns gate rows r = g*16 + fi <-> W_hh row (g*768 + nb*16 + fi).
__global__ void pack_whh(const float* __restrict__ W) {
    size_t idx = (size_t)blockIdx.x * 256 + threadIdx.x;
    if (idx >= (size_t)GG * FH) return;
    int k   = (int)(idx % FH);
    int row = (int)(idx / FH);       // nb*64 + r
    int nb = row >> 6, r = row & 63;
    int g = r >> 4, fi = r & 15;
    g_Whp[idx] = __float2half(W[(size_t)(g * FH + nb * 16 + fi) * FH + k]);
}

// ---------------- GAT: one warp per graph, writes fp16 X ----------------
__global__ __launch_bounds__(256) void gat_kernel(
    const float* __restrict__ src,
    const float* __restrict__ W_pre, const float* __restrict__ b_pre,
    const float* __restrict__ W_gat,
    const float* __restrict__ att_src, const float* __restrict__ att_dst,
    const float* __restrict__ b_gat,
    __half* __restrict__ Xp)
{
    __shared__ float Wg[32 * 32];
    __shared__ float xbuf[8][24][32];
    __shared__ float asd[8][24][2];

    int tid = threadIdx.x;
    for (int i = tid; i < 1024; i += 256) Wg[i] = W_gat[i];
    __syncthreads();

    int w = tid >> 5, h = tid & 31;
    int b = blockIdx.x * 8 + w;
    int n = b >> 8, l = b & 255;

    const float* s = src + (size_t)b * 72;
    float w0 = W_pre[h], w1 = W_pre[32 + h], w2 = W_pre[64 + h], bp = b_pre[h];

    #pragma unroll
    for (int j = 0; j < 24; j++) {
        float v = fmaf(s[j*3+2], w2, fmaf(s[j*3+1], w1, fmaf(s[j*3+0], w0, bp)));
        xbuf[w][j][h] = tanhf(v);
    }
    __syncwarp();

    float asrc = att_src[h], adst = att_dst[h];
    #pragma unroll
    for (int j = 0; j < 24; j++) {
        float acc = 0.f;
        #pragma unroll
        for (int k = 0; k < 32; k++) acc = fmaf(xbuf[w][j][k], Wg[k*32 + h], acc);
        float ps = acc * asrc, pd = acc * adst;
        #pragma unroll
        for (int o = 16; o > 0; o >>= 1) {
            ps += __shfl_xor_sync(0xffffffffu, ps, o);
            pd += __shfl_xor_sync(0xffffffffu, pd, o);
        }
        __syncwarp();
        xbuf[w][j][h] = acc;
        if (h == 0) { asd[w][j][0] = ps; asd[w][j][1] = pd; }
    }
    __syncwarp();

    float bg = b_gat[h];
    size_t rbase = (size_t)(l * 128 + n) * KH;
    #pragma unroll
    for (int j = 0; j < 24; j++) {
        int p = c_par[j];
        float g;
        if (p < 0) {
            g = xbuf[w][j][h];
        } else {
            float ad = asd[w][j][1];
            float es = ad + asd[w][j][0];
            float ep = ad + asd[w][p][0];
            es = es > 0.f ? es : 0.2f * es;
            ep = ep > 0.f ? ep : 0.2f * ep;
            float m  = fmaxf(es, ep);
            float ws = expf(es - m), wp = expf(ep - m);
            float inv = 1.f / (ws + wp);
            g = (ws * xbuf[w][j][h] + wp * xbuf[w][p][h]) * inv;
        }
        Xp[rbase + j * 32 + h] = __float2half(g + bg);
    }
}

// ---------------- mega kernel ----------------
__global__ __launch_bounds__(256, 1) void mega(
    const float* __restrict__ bih, const float* __restrict__ bhh,
    float* __restrict__ out)
{
    extern __shared__ __align__(16) char sm[];
    const uint32_t smb = smem_u32(sm);

    const int tid  = threadIdx.x;
    const int lane = tid & 31;
    const int warp = tid >> 5;

    if (blockIdx.x >= NRB) {
        // ================= producer role: 1-term fp16 GEMM =================
        const int gb = blockIdx.x - NRB;
        const __half* Ap = g_Xp;
        const __half* Bp = g_Wp;
        float* C = g_XW;

        const int wm = warp >> 2;
        const int wn = warp & 3;
        const int ldRow = tid >> 2;
        const int ldSeg = tid & 3;
        const uint32_t stRow = ldRow * ROWB + ldSeg * 16;
        const uint32_t aOff = (uint32_t)((wm * 64 + (lane & 7) + ((lane >> 3) & 1) * 8) * ROWB
                                         + ((lane >> 4) & 1) * 16);
        const uint32_t bOff = (uint32_t)(ATILE + (wn * 32 + (lane & 7) + ((lane >> 4) & 1) * 8) * ROWB
                                         + ((lane >> 3) & 1) * 16);

        for (int tile = gb; tile < NTILE; tile += NGB) {
            const int y = tile / 24;
            const int x = tile % 24;
            const int m0 = y * 128;
            const int n0 = x * 128;

            const __half* gA = Ap + (size_t)(m0 + ldRow) * KH + ldSeg * 8;
            const __half* gB = Bp + (size_t)(n0 + ldRow) * KH + ldSeg * 8;

            float acc[4][4][4];
            #pragma unroll
            for (int i = 0; i < 4; i++)
                #pragma unroll
                for (int j = 0; j < 4; j++)
                    #pragma unroll
                    for (int q = 0; q < 4; q++) acc[i][j][q] = 0.f;

            #pragma unroll
            for (int pc = 0; pc < GNST - 1; pc++) {
                uint32_t sb = smb + pc * STAGEB;
                int ko = pc * BK;
                #pragma unroll
                for (int i = 0; i < 2; i++) {
                    cp16(sb + stRow + i * 64 * ROWB,         gA + (size_t)i * 64 * KH + ko);
                    cp16(sb + ATILE + stRow + i * 64 * ROWB, gB + (size_t)i * 64 * KH + ko);
                }
                asm volatile("cp.async.commit_group;");
            }

            for (int kc = 0; kc < NKH; kc++) {
                asm volatile("cp.async.wait_group %0;" :: "n"(GNST - 2));
                __syncthreads();

                if (kc + GNST - 1 < NKH) {
                    uint32_t sb = smb + ((kc + GNST - 1) & (GNST - 1)) * STAGEB;
                    int ko = (kc + GNST - 1) * BK;
                    #pragma unroll
                    for (int i = 0; i < 2; i++) {
                        cp16(sb + stRow + i * 64 * ROWB,         gA + (size_t)i * 64 * KH + ko);
                        cp16(sb + ATILE + stRow + i * 64 * ROWB, gB + (size_t)i * 64 * KH + ko);
                    }
                }
                asm volatile("cp.async.commit_group;");

                const uint32_t soff = smb + (kc & (GNST - 1)) * STAGEB;
                #pragma unroll
                for (int ks = 0; ks < 2; ks++) {
                    uint32_t a[4][4], bq[4][2];
                    #pragma unroll
                    for (int tm = 0; tm < 4; tm++)
                        ldm_x4(a[tm][0], a[tm][1], a[tm][2], a[tm][3],
                               soff + aOff + tm * (16 * ROWB) + ks * 32);
                    #pragma unroll
                    for (int tb = 0; tb < 2; tb++) {
                        uint32_t r0, r1, r2, r3;
                        ldm_x4(r0, r1, r2, r3, soff + bOff + tb * (16 * ROWB) + ks * 32);
                        bq[2*tb][0] = r0; bq[2*tb][1] = r1;
                        bq[2*tb+1][0] = r2; bq[2*tb+1][1] = r3;
                    }
                    #pragma unroll
                    for (int tm = 0; tm < 4; tm++)
                        #pragma unroll
                        for (int tn = 0; tn < 4; tn++)
                            mma_f16(acc[tm][tn], a[tm], bq[tn]);
                }
            }
            asm volatile("cp.async.wait_group 0;");

            #pragma unroll
            for (int tm = 0; tm < 4; tm++) {
                int row = m0 + wm * 64 + tm * 16 + (lane >> 2);
                #pragma unroll
                for (int tn = 0; tn < 4; tn++) {
                    int col = n0 + wn * 32 + tn * 8 + (lane & 3) * 2;
                    float* p = C + (size_t)row * GG + col;
                    *(float2*)p                    = make_float2(acc[tm][tn][0], acc[tm][tn][1]);
                    *(float2*)(p + (size_t)8 * GG) = make_float2(acc[tm][tn][2], acc[tm][tn][3]);
                }
            }

            __threadfence();
            __syncthreads();
            if (tid == 0) atomicAdd(&g_flag[y], 1);
            __syncthreads();
        }
        return;
    }

    // ====== consumer role: persistent LSTM (1-term, 64x64, full-resident A) ======
    const int b  = blockIdx.x;
    const int mb = b & 1;
    const int nb = b >> 1;
    const int m0 = mb * 64;

    const int wm = warp >> 2;        // 0..1: 32-row m strip
    const int wn = warp & 3;         // 0..3: 16-row n strip

    const int efi = tid & 15;
    const int em0 = tid >> 4;        // 0..15
    const int feat = nb * 16 + efi;

    // one-time resident W slice (12 chunks x 64 rows x 64 halfs)
    {
        const __half* Wb = g_Whp + (size_t)nb * 64 * FH;
        for (int i = tid; i < NWCH * 512; i += 256) {
            int chunk = i >> 9;
            int rem   = i & 511;
            int row   = rem >> 3, seg = rem & 7;
            cp16(smb + WBASE + chunk * WCHB + row * RROW + seg * 16,
                 Wb + (size_t)row * FH + chunk * RBK + seg * 8);
        }
        asm volatile("cp.async.commit_group;");
        asm volatile("cp.async.wait_group 0;");
    }

    float bias_r[4];
    #pragma unroll
    for (int g = 0; g < 4; g++) bias_r[g] = bih[g * FH + feat] + bhh[g * FH + feat];

    float creg[4] = {0.f, 0.f, 0.f, 0.f};

    __syncthreads();

    const uint32_t aOff = (uint32_t)((wm * 32 + (lane & 15)) * RROW
                                     + ((lane >> 4) & 1) * 16);
    const uint32_t bOffW = (uint32_t)((wn * 16 + (lane & 7) + ((lane >> 4) & 1) * 8) * RROW
                                      + ((lane >> 3) & 1) * 16);

    unsigned* ctr = &g_ctr2[mb][0];
    const float* xwbase = g_XW;

    for (int t = 0; t < LT; t++) {
        const __half* hin   = g_hp[(t + 1) & 1];
        __half*       houtp = g_hp[t & 1];
        const float*  xw    = xwbase + (size_t)t * NB * GG;

        // ---- combined waits: xw[t] tiles ready + same-half h[t-1] published ----
        if (tid == 0) {
            while (*(volatile int*)&g_flag[t] < 24) { __nanosleep(128); }
            if (t > 0) {
                unsigned target = 48u * (unsigned)t;
                while (*(volatile unsigned*)ctr < target) { __nanosleep(64); }
            }
            __threadfence();
        }
        __syncthreads();

        // xw prefetch for this step's cells
        float xwv[4][4];
        #pragma unroll
        for (int i = 0; i < 4; i++) {
            const float* xwr = xw + (size_t)(m0 + em0 + i * 16) * GG + feat;
            xwv[i][0] = xwr[0];
            xwv[i][1] = xwr[FH];
            xwv[i][2] = xwr[2 * FH];
            xwv[i][3] = xwr[3 * FH];
        }

        float acc[2][2][4];
        #pragma unroll
        for (int i = 0; i < 2; i++)
            #pragma unroll
            for (int j = 0; j < 2; j++)
                #pragma unroll
                for (int q = 0; q < 4; q++) acc[i][j][q] = 0.f;

        if (t > 0) {
            // ---- load ALL 12 h-chunks in two commit groups ----
            // group A: chunks 0..5 (i < 3072), group B: chunks 6..11
            #pragma unroll
            for (int j = 0; j < 12; j++) {
                int i = tid + j * 256;
                int chunk = i >> 9;
                int rem   = i & 511;
                int row   = rem >> 3, seg = rem & 7;
                cp16(smb + chunk * ACHB + row * RROW + seg * 16,
                     hin + (size_t)(m0 + row) * FH + chunk * RBK + seg * 8);
            }
            asm volatile("cp.async.commit_group;");
            #pragma unroll
            for (int j = 12; j < 24; j++) {
                int i = tid + j * 256;
                int chunk = i >> 9;
                int rem   = i & 511;
                int row   = rem >> 3, seg = rem & 7;
                cp16(smb + chunk * ACHB + row * RROW + seg * 16,
                     hin + (size_t)(m0 + row) * FH + chunk * RBK + seg * 8);
            }
            asm volatile("cp.async.commit_group;");

            // ---- MMA chunks 0..5 under group-B load ----
            asm volatile("cp.async.wait_group 1;");
            __syncthreads();
            #pragma unroll
            for (int kc = 0; kc < 6; kc++) {
                const uint32_t soff = smb + kc * ACHB;
                const uint32_t woff = smb + WBASE + kc * WCHB;
                #pragma unroll
                for (int ks = 0; ks < RBK / 16; ks++) {
                    uint32_t a[2][4], bq[2][2];
                    #pragma unroll
                    for (int tm = 0; tm < 2; tm++)
                        ldm_x4(a[tm][0], a[tm][1], a[tm][2], a[tm][3],
                               soff + aOff + tm * (16 * RROW) + ks * 32);
                    {
                        uint32_t r0, r1, r2, r3;
                        ldm_x4(r0, r1, r2, r3, woff + bOffW + ks * 32);
                        bq[0][0] = r0; bq[0][1] = r1;
                        bq[1][0] = r2; bq[1][1] = r3;
                    }
                    #pragma unroll
                    for (int tm = 0; tm < 2; tm++)
                        #pragma unroll
                        for (int tn = 0; tn < 2; tn++)
                            mma_f16(acc[tm][tn], a[tm], bq[tn]);
                }
            }

            // ---- MMA chunks 6..11 ----
            asm volatile("cp.async.wait_group 0;");
            __syncthreads();
            #pragma unroll
            for (int kc = 6; kc < 12; kc++) {
                const uint32_t soff = smb + kc * ACHB;
                const uint32_t woff = smb + WBASE + kc * WCHB;
                #pragma unroll
                for (int ks = 0; ks < RBK / 16; ks++) {
                    uint32_t a[2][4], bq[2][2];
                    #pragma unroll
                    for (int tm = 0; tm < 2; tm++)
                        ldm_x4(a[tm][0], a[tm][1], a[tm][2], a[tm][3],
                               soff + aOff + tm * (16 * RROW) + ks * 32);
                    {
                        uint32_t r0, r1, r2, r3;
                        ldm_x4(r0, r1, r2, r3, woff + bOffW + ks * 32);
                        bq[0][0] = r0; bq[0][1] = r1;
                        bq[1][0] = r2; bq[1][1] = r3;
                    }
                    #pragma unroll
                    for (int tm = 0; tm < 2; tm++)
                        #pragma unroll
                        for (int tn = 0; tn < 2; tn++)
                            mma_f16(acc[tm][tn], a[tm], bq[tn]);
                }
            }
        }
        __syncthreads();

        // gate tile: Gt[64 n][65 m] fp32 (overlays A chunks 0-1)
        float* Gt = (float*)sm;
        #pragma unroll
        for (int tm = 0; tm < 2; tm++) {
            int m = wm * 32 + tm * 16 + (lane >> 2);
            #pragma unroll
            for (int tn = 0; tn < 2; tn++) {
                int n = wn * 16 + tn * 8 + (lane & 3) * 2;
                Gt[n * 65 + m]           = acc[tm][tn][0];
                Gt[(n + 1) * 65 + m]     = acc[tm][tn][1];
                Gt[n * 65 + m + 8]       = acc[tm][tn][2];
                Gt[(n + 1) * 65 + m + 8] = acc[tm][tn][3];
            }
        }
        __syncthreads();

        // pointwise: 16 feat x 64 m, 4 cells/thread; publish h, arrive, then out
        float hvv[4];
        #pragma unroll
        for (int i = 0; i < 4; i++) {
            int ml = em0 + i * 16;
            int m  = m0 + ml;

            float gi = Gt[(0*16 + efi) * 65 + ml] + xwv[i][0] + bias_r[0];
            float gf = Gt[(1*16 + efi) * 65 + ml] + xwv[i][1] + bias_r[1];
            float gg = Gt[(2*16 + efi) * 65 + ml] + xwv[i][2] + bias_r[2];
            float go = Gt[(3*16 + efi) * 65 + ml] + xwv[i][3] + bias_r[3];

            float c  = sigm(gf) * creg[i] + sigm(gi) * tanhf(gg);
            float hv = sigm(go) * tanhf(c);
            creg[i] = c;
            hvv[i] = hv;

            houtp[(size_t)m * FH + feat] = __float2half(hv);
        }

        __threadfence();
        __syncthreads();
        if (tid == 0) atomicAdd(ctr, 1u);

        #pragma unroll
        for (int i = 0; i < 4; i++) {
            int m = m0 + em0 + i * 16;
            out[((size_t)m * LT + t) * FH + feat] = hvv[i];
            if (t == LT - 1) {
                out[(size_t)NB * LT * FH + (size_t)m * FH + feat]           = hvv[i];
                out[(size_t)NB * LT * FH + NB * FH + (size_t)m * FH + feat] = creg[i];
            }
        }
    }
}

// ---------------- launch ----------------
extern "C" void kernel_launch(void* const* d_in, const int* in_sizes, int n_in,
                              void* d_out, int out_size)
{
    const float* src     = (const float*)d_in[0];
    const float* W_pre   = (const float*)d_in[1];
    const float* b_pre   = (const float*)d_in[2];
    const float* W_gat   = (const float*)d_in[3];
    const float* att_src = (const float*)d_in[4];
    const float* att_dst = (const float*)d_in[5];
    const float* b_gat   = (const float*)d_in[6];
    const float* W_ih    = (const float*)d_in[7];
    const float* W_hh    = (const float*)d_in[8];
    const float* b_ih    = (const float*)d_in[9];
    const float* b_hh    = (const float*)d_in[10];
    float* out = (float*)d_out;

    __half *Xp, *Wp;
    cudaGetSymbolAddress((void**)&Xp,  g_Xp);
    cudaGetSymbolAddress((void**)&Wp,  g_Wp);

    cudaFuncSetAttribute(mega, cudaFuncAttributeMaxDynamicSharedMemorySize,
                         MEGA_SMEM);

    // 0) prep
    reset_flags<<<1, 256>>>();
    pack_w<<<(GG * FH + 255) / 256, 256>>>(W_ih, Wp);
    pack_whh<<<(unsigned)(((size_t)GG * FH + 255) / 256), 256>>>(W_hh);

    // 1) GAT -> fp16 X
    gat_kernel<<<BG / 8, 256>>>(src, W_pre, b_pre, W_gat, att_src, att_dst, b_gat, Xp);

    // 2) fused producer-GEMM + persistent-LSTM
    mega<<<NRB + NGB, 256, MEGA_SMEM>>>(b_ih, b_hh, out);
}

// round 15
// speedup vs baseline: 3.4766x; 1.0543x over previous
#include <cuda_runtime.h>
#include <cuda_fp16.h>
#include <math.h>
#include <stdint.h>

// ---------------- problem constants ----------------
#define NB   128
#define LT   256
#define FH   768
#define GG   3072
#define BG   (NB*LT)

// ---- big hoisted GEMM (1-term fp16, K=768) ----
#define KH   FH              // 768
#define BK   32
#define NKH  (KH/BK)         // 24
#define ROWB 80
#define ATILE (128*ROWB)
#define STAGEB (2*ATILE)     // 20480
#define GNST 8

// ---- persistent recurrent role (1-term fp16 h, 64x64 tiles, full-resident A) ----
#define RBK   64
#define RNCH  12             // 12 A chunks (K=768)
#define NWCH  12             // 12 W chunks
#define RROW  144
#define ACHB  (64*RROW)      // 9216 per A chunk
#define WBASE (RNCH*ACHB)    // 110592
#define WCHB  (64*RROW)      // 9216 per W chunk
#define PSMEM (WBASE + NWCH*WCHB)   // 221184
#define NRB   96
#define NGB   52
#define NTILE (24*LT)
#define MEGA_SMEM PSMEM      // >= GNST*STAGEB (163840)

// ---------------- scratch (device globals) ----------------
__device__ __half g_Xp [(size_t)BG * KH];     // GAT out, fp16
__device__ __half g_Wp [(size_t)GG * KH];     // W_ih fp16
__device__ __half g_Whp[(size_t)GG * FH];     // permuted W_hh fp16
__device__ __half g_hp [2][(size_t)NB * FH];  // ping-pong h, fp16
__device__ float  g_XW [(size_t)BG * GG];
__device__ unsigned g_ctr2[2][32];            // per-m-half barrier counters (padded)
__device__ int      g_flag[LT];

__constant__ int c_par[24] = {-1,0,0,0,1,2,3,4,5,6,7,8,9,9,9,12,13,14,16,17,18,19,20,21};

// fast MUFU-based activations (sign-safe)
__device__ __forceinline__ float fsigm(float x) {
    float e = __expf(-x);
    return __fdividef(1.f, 1.f + e);
}
__device__ __forceinline__ float ftanh(float x) {
    float a = fabsf(x);
    float e = __expf(-2.f * a);
    float r = __fdividef(1.f - e, 1.f + e);
    return copysignf(r, x);
}

__device__ __forceinline__ uint32_t smem_u32(const void* p) {
    uint32_t a;
    asm("{ .reg .u64 t; cvta.to.shared.u64 t, %1; cvt.u32.u64 %0, t; }" : "=r"(a) : "l"(p));
    return a;
}

__device__ __forceinline__ void cp16(uint32_t s, const void* g) {
    asm volatile("cp.async.cg.shared.global [%0], [%1], 16;" :: "r"(s), "l"(g));
}

__device__ __forceinline__ void ldm_x4(uint32_t &r0, uint32_t &r1, uint32_t &r2,
                                       uint32_t &r3, uint32_t addr) {
    asm volatile("ldmatrix.sync.aligned.m8n8.x4.shared.b16 {%0,%1,%2,%3}, [%4];"
                 : "=r"(r0), "=r"(r1), "=r"(r2), "=r"(r3) : "r"(addr));
}

__device__ __forceinline__ void mma_f16(float* d, const uint32_t* a,
                                        const uint32_t* b) {
    asm volatile(
        "mma.sync.aligned.m16n8k16.row.col.f32.f16.f16.f32 "
        "{%0,%1,%2,%3}, {%4,%5,%6,%7}, {%8,%9}, {%0,%1,%2,%3};"
        : "+f"(d[0]), "+f"(d[1]), "+f"(d[2]), "+f"(d[3])
        : "r"(a[0]), "r"(a[1]), "r"(a[2]), "r"(a[3]), "r"(b[0]), "r"(b[1]));
}

// ---------------- small prep kernels ----------------
__global__ void reset_flags() {
    int i = threadIdx.x;
    if (i < 64) ((unsigned*)g_ctr2)[i] = 0u;
    if (i < LT) g_flag[i] = 0;
}

__global__ void pack_w(const float* __restrict__ W, __half* __restrict__ Wp) {
    int i = blockIdx.x * 256 + threadIdx.x;
    if (i >= GG * FH) return;
    Wp[i] = __float2half(W[i]);
}

// Block nb owns gate rows r = g*16 + fi <-> W_hh row (g*768 + nb*16 + fi).
__global__ void pack_whh(const float* __restrict__ W) {
    size_t idx = (size_t)blockIdx.x * 256 + threadIdx.x;
    if (idx >= (size_t)GG * FH) return;
    int k   = (int)(idx % FH);
    int row = (int)(idx / FH);       // nb*64 + r
    int nb = row >> 6, r = row & 63;
    int g = r >> 4, fi = r & 15;
    g_Whp[idx] = __float2half(W[(size_t)(g * FH + nb * 16 + fi) * FH + k]);
}

// ---------------- GAT: one warp per graph (k-outer matmul) ----------------
__global__ __launch_bounds__(256) void gat_kernel(
    const float* __restrict__ src,
    const float* __restrict__ W_pre, const float* __restrict__ b_pre,
    const float* __restrict__ W_gat,
    const float* __restrict__ att_src, const float* __restrict__ att_dst,
    const float* __restrict__ b_gat,
    __half* __restrict__ Xp)
{
    __shared__ float Wg[32 * 32];
    __shared__ float xbuf[8][24][32];
    __shared__ float asd[8][24][2];

    int tid = threadIdx.x;
    for (int i = tid; i < 1024; i += 256) Wg[i] = W_gat[i];
    __syncthreads();

    int w = tid >> 5, h = tid & 31;
    int b = blockIdx.x * 8 + w;
    int n = b >> 8, l = b & 255;

    const float* s = src + (size_t)b * 72;
    float w0 = W_pre[h], w1 = W_pre[32 + h], w2 = W_pre[64 + h], bp = b_pre[h];

    #pragma unroll
    for (int j = 0; j < 24; j++) {
        float v = fmaf(s[j*3+2], w2, fmaf(s[j*3+1], w1, fmaf(s[j*3+0], w0, bp)));
        xbuf[w][j][h] = tanhf(v);
    }
    __syncwarp();

    // k-outer matmul: accj[j] = sum_k xbuf[j][k] * Wg[k][h]
    float accj[24];
    #pragma unroll
    for (int j = 0; j < 24; j++) accj[j] = 0.f;
    #pragma unroll
    for (int k = 0; k < 32; k++) {
        float wv = Wg[k * 32 + h];
        #pragma unroll
        for (int j = 0; j < 24; j++)
            accj[j] = fmaf(xbuf[w][j][k], wv, accj[j]);
    }
    __syncwarp();   // all lanes done reading xbuf

    float asrc = att_src[h], adst = att_dst[h];
    #pragma unroll
    for (int j = 0; j < 24; j++) {
        float ps = accj[j] * asrc, pd = accj[j] * adst;
        #pragma unroll
        for (int o = 16; o > 0; o >>= 1) {
            ps += __shfl_xor_sync(0xffffffffu, ps, o);
            pd += __shfl_xor_sync(0xffffffffu, pd, o);
        }
        if (h == 0) { asd[w][j][0] = ps; asd[w][j][1] = pd; }
        xbuf[w][j][h] = accj[j];   // xp in place
    }
    __syncwarp();

    float bg = b_gat[h];
    size_t rbase = (size_t)(l * 128 + n) * KH;
    #pragma unroll
    for (int j = 0; j < 24; j++) {
        int p = c_par[j];
        float g;
        if (p < 0) {
            g = xbuf[w][j][h];
        } else {
            float ad = asd[w][j][1];
            float es = ad + asd[w][j][0];
            float ep = ad + asd[w][p][0];
            es = es > 0.f ? es : 0.2f * es;
            ep = ep > 0.f ? ep : 0.2f * ep;
            float m  = fmaxf(es, ep);
            float ws = __expf(es - m), wp = __expf(ep - m);
            float inv = __fdividef(1.f, ws + wp);
            g = (ws * xbuf[w][j][h] + wp * xbuf[w][p][h]) * inv;
        }
        Xp[rbase + j * 32 + h] = __float2half(g + bg);
    }
}

// ---------------- mega kernel ----------------
__global__ __launch_bounds__(256, 1) void mega(
    const float* __restrict__ bih, const float* __restrict__ bhh,
    float* __restrict__ out)
{
    extern __shared__ __align__(16) char sm[];
    const uint32_t smb = smem_u32(sm);

    const int tid  = threadIdx.x;
    const int lane = tid & 31;
    const int warp = tid >> 5;

    if (blockIdx.x >= NRB) {
        // ================= producer role: 1-term fp16 GEMM =================
        const int gb = blockIdx.x - NRB;
        const __half* Ap = g_Xp;
        const __half* Bp = g_Wp;
        float* C = g_XW;

        const int wm = warp >> 2;
        const int wn = warp & 3;
        const int ldRow = tid >> 2;
        const int ldSeg = tid & 3;
        const uint32_t stRow = ldRow * ROWB + ldSeg * 16;
        const uint32_t aOff = (uint32_t)((wm * 64 + (lane & 7) + ((lane >> 3) & 1) * 8) * ROWB
                                         + ((lane >> 4) & 1) * 16);
        const uint32_t bOff = (uint32_t)(ATILE + (wn * 32 + (lane & 7) + ((lane >> 4) & 1) * 8) * ROWB
                                         + ((lane >> 3) & 1) * 16);

        for (int tile = gb; tile < NTILE; tile += NGB) {
            const int y = tile / 24;
            const int x = tile % 24;
            const int m0 = y * 128;
            const int n0 = x * 128;

            const __half* gA = Ap + (size_t)(m0 + ldRow) * KH + ldSeg * 8;
            const __half* gB = Bp + (size_t)(n0 + ldRow) * KH + ldSeg * 8;

            float acc[4][4][4];
            #pragma unroll
            for (int i = 0; i < 4; i++)
                #pragma unroll
                for (int j = 0; j < 4; j++)
                    #pragma unroll
                    for (int q = 0; q < 4; q++) acc[i][j][q] = 0.f;

            #pragma unroll
            for (int pc = 0; pc < GNST - 1; pc++) {
                uint32_t sb = smb + pc * STAGEB;
                int ko = pc * BK;
                #pragma unroll
                for (int i = 0; i < 2; i++) {
                    cp16(sb + stRow + i * 64 * ROWB,         gA + (size_t)i * 64 * KH + ko);
                    cp16(sb + ATILE + stRow + i * 64 * ROWB, gB + (size_t)i * 64 * KH + ko);
                }
                asm volatile("cp.async.commit_group;");
            }

            for (int kc = 0; kc < NKH; kc++) {
                asm volatile("cp.async.wait_group %0;" :: "n"(GNST - 2));
                __syncthreads();

                if (kc + GNST - 1 < NKH) {
                    uint32_t sb = smb + ((kc + GNST - 1) & (GNST - 1)) * STAGEB;
                    int ko = (kc + GNST - 1) * BK;
                    #pragma unroll
                    for (int i = 0; i < 2; i++) {
                        cp16(sb + stRow + i * 64 * ROWB,         gA + (size_t)i * 64 * KH + ko);
                        cp16(sb + ATILE + stRow + i * 64 * ROWB, gB + (size_t)i * 64 * KH + ko);
                    }
                }
                asm volatile("cp.async.commit_group;");

                const uint32_t soff = smb + (kc & (GNST - 1)) * STAGEB;
                #pragma unroll
                for (int ks = 0; ks < 2; ks++) {
                    uint32_t a[4][4], bq[4][2];
                    #pragma unroll
                    for (int tm = 0; tm < 4; tm++)
                        ldm_x4(a[tm][0], a[tm][1], a[tm][2], a[tm][3],
                               soff + aOff + tm * (16 * ROWB) + ks * 32);
                    #pragma unroll
                    for (int tb = 0; tb < 2; tb++) {
                        uint32_t r0, r1, r2, r3;
                        ldm_x4(r0, r1, r2, r3, soff + bOff + tb * (16 * ROWB) + ks * 32);
                        bq[2*tb][0] = r0; bq[2*tb][1] = r1;
                        bq[2*tb+1][0] = r2; bq[2*tb+1][1] = r3;
                    }
                    #pragma unroll
                    for (int tm = 0; tm < 4; tm++)
                        #pragma unroll
                        for (int tn = 0; tn < 4; tn++)
                            mma_f16(acc[tm][tn], a[tm], bq[tn]);
                }
            }
            asm volatile("cp.async.wait_group 0;");

            #pragma unroll
            for (int tm = 0; tm < 4; tm++) {
                int row = m0 + wm * 64 + tm * 16 + (lane >> 2);
                #pragma unroll
                for (int tn = 0; tn < 4; tn++) {
                    int col = n0 + wn * 32 + tn * 8 + (lane & 3) * 2;
                    float* p = C + (size_t)row * GG + col;
                    *(float2*)p                    = make_float2(acc[tm][tn][0], acc[tm][tn][1]);
                    *(float2*)(p + (size_t)8 * GG) = make_float2(acc[tm][tn][2], acc[tm][tn][3]);
                }
            }

            __threadfence();
            __syncthreads();
            if (tid == 0) atomicAdd(&g_flag[y], 1);
            __syncthreads();
        }
        return;
    }

    // ====== consumer role: persistent LSTM (1-term, 64x64, full-resident A) ======
    const int b  = blockIdx.x;
    const int mb = b & 1;
    const int nb = b >> 1;
    const int m0 = mb * 64;

    const int wm = warp >> 2;        // 0..1: 32-row m strip
    const int wn = warp & 3;         // 0..3: 16-row n strip

    const int efi = tid & 15;
    const int em0 = tid >> 4;        // 0..15
    const int feat = nb * 16 + efi;

    // one-time resident W slice (12 chunks x 64 rows x 64 halfs)
    {
        const __half* Wb = g_Whp + (size_t)nb * 64 * FH;
        for (int i = tid; i < NWCH * 512; i += 256) {
            int chunk = i >> 9;
            int rem   = i & 511;
            int row   = rem >> 3, seg = rem & 7;
            cp16(smb + WBASE + chunk * WCHB + row * RROW + seg * 16,
                 Wb + (size_t)row * FH + chunk * RBK + seg * 8);
        }
        asm volatile("cp.async.commit_group;");
        asm volatile("cp.async.wait_group 0;");
    }

    float bias_r[4];
    #pragma unroll
    for (int g = 0; g < 4; g++) bias_r[g] = bih[g * FH + feat] + bhh[g * FH + feat];

    float creg[4] = {0.f, 0.f, 0.f, 0.f};

    __syncthreads();

    const uint32_t aOff = (uint32_t)((wm * 32 + (lane & 15)) * RROW
                                     + ((lane >> 4) & 1) * 16);
    const uint32_t bOffW = (uint32_t)((wn * 16 + (lane & 7) + ((lane >> 4) & 1) * 8) * RROW
                                      + ((lane >> 3) & 1) * 16);

    unsigned* ctr = &g_ctr2[mb][0];
    const float* xwbase = g_XW;

    for (int t = 0; t < LT; t++) {
        const __half* hin   = g_hp[(t + 1) & 1];
        __half*       houtp = g_hp[t & 1];
        const float*  xw    = xwbase + (size_t)t * NB * GG;

        // ---- combined waits: xw[t] tiles ready + same-half h[t-1] published ----
        if (tid == 0) {
            while (*(volatile int*)&g_flag[t] < 24) { __nanosleep(64); }
            if (t > 0) {
                unsigned target = 48u * (unsigned)t;
                while (*(volatile unsigned*)ctr < target) { __nanosleep(32); }
            }
            __threadfence();
        }
        __syncthreads();

        // ---- issue h loads FIRST so xw LDG overlaps them ----
        if (t > 0) {
            #pragma unroll
            for (int j = 0; j < 12; j++) {
                int i = tid + j * 256;
                int chunk = i >> 9;
                int rem   = i & 511;
                int row   = rem >> 3, seg = rem & 7;
                cp16(smb + chunk * ACHB + row * RROW + seg * 16,
                     hin + (size_t)(m0 + row) * FH + chunk * RBK + seg * 8);
            }
            asm volatile("cp.async.commit_group;");
            #pragma unroll
            for (int j = 12; j < 24; j++) {
                int i = tid + j * 256;
                int chunk = i >> 9;
                int rem   = i & 511;
                int row   = rem >> 3, seg = rem & 7;
                cp16(smb + chunk * ACHB + row * RROW + seg * 16,
                     hin + (size_t)(m0 + row) * FH + chunk * RBK + seg * 8);
            }
            asm volatile("cp.async.commit_group;");
        }

        // xw prefetch (overlaps cp.async)
        float xwv[4][4];
        #pragma unroll
        for (int i = 0; i < 4; i++) {
            const float* xwr = xw + (size_t)(m0 + em0 + i * 16) * GG + feat;
            xwv[i][0] = xwr[0];
            xwv[i][1] = xwr[FH];
            xwv[i][2] = xwr[2 * FH];
            xwv[i][3] = xwr[3 * FH];
        }

        float acc[2][2][4];
        #pragma unroll
        for (int i = 0; i < 2; i++)
            #pragma unroll
            for (int j = 0; j < 2; j++)
                #pragma unroll
                for (int q = 0; q < 4; q++) acc[i][j][q] = 0.f;

        if (t > 0) {
            // ---- MMA chunks 0..5 under group-B load ----
            asm volatile("cp.async.wait_group 1;");
            __syncthreads();
            #pragma unroll
            for (int kc = 0; kc < 6; kc++) {
                const uint32_t soff = smb + kc * ACHB;
                const uint32_t woff = smb + WBASE + kc * WCHB;
                #pragma unroll
                for (int ks = 0; ks < RBK / 16; ks++) {
                    uint32_t a[2][4], bq[2][2];
                    #pragma unroll
                    for (int tm = 0; tm < 2; tm++)
                        ldm_x4(a[tm][0], a[tm][1], a[tm][2], a[tm][3],
                               soff + aOff + tm * (16 * RROW) + ks * 32);
                    {
                        uint32_t r0, r1, r2, r3;
                        ldm_x4(r0, r1, r2, r3, woff + bOffW + ks * 32);
                        bq[0][0] = r0; bq[0][1] = r1;
                        bq[1][0] = r2; bq[1][1] = r3;
                    }
                    #pragma unroll
                    for (int tm = 0; tm < 2; tm++)
                        #pragma unroll
                        for (int tn = 0; tn < 2; tn++)
                            mma_f16(acc[tm][tn], a[tm], bq[tn]);
                }
            }

            // ---- MMA chunks 6..11 ----
            asm volatile("cp.async.wait_group 0;");
            __syncthreads();
            #pragma unroll
            for (int kc = 6; kc < 12; kc++) {
                const uint32_t soff = smb + kc * ACHB;
                const uint32_t woff = smb + WBASE + kc * WCHB;
                #pragma unroll
                for (int ks = 0; ks < RBK / 16; ks++) {
                    uint32_t a[2][4], bq[2][2];
                    #pragma unroll
                    for (int tm = 0; tm < 2; tm++)
                        ldm_x4(a[tm][0], a[tm][1], a[tm][2], a[tm][3],
                               soff + aOff + tm * (16 * RROW) + ks * 32);
                    {
                        uint32_t r0, r1, r2, r3;
                        ldm_x4(r0, r1, r2, r3, woff + bOffW + ks * 32);
                        bq[0][0] = r0; bq[0][1] = r1;
                        bq[1][0] = r2; bq[1][1] = r3;
                    }
                    #pragma unroll
                    for (int tm = 0; tm < 2; tm++)
                        #pragma unroll
                        for (int tn = 0; tn < 2; tn++)
                            mma_f16(acc[tm][tn], a[tm], bq[tn]);
                }
            }
        }
        __syncthreads();

        // gate tile: Gt[64 n][65 m] fp32 (overlays A chunks 0-1)
        float* Gt = (float*)sm;
        #pragma unroll
        for (int tm = 0; tm < 2; tm++) {
            int m = wm * 32 + tm * 16 + (lane >> 2);
            #pragma unroll
            for (int tn = 0; tn < 2; tn++) {
                int n = wn * 16 + tn * 8 + (lane & 3) * 2;
                Gt[n * 65 + m]           = acc[tm][tn][0];
                Gt[(n + 1) * 65 + m]     = acc[tm][tn][1];
                Gt[n * 65 + m + 8]       = acc[tm][tn][2];
                Gt[(n + 1) * 65 + m + 8] = acc[tm][tn][3];
            }
        }
        __syncthreads();

        // pointwise: 16 feat x 64 m, 4 cells/thread; publish h, arrive, then out
        float hvv[4];
        #pragma unroll
        for (int i = 0; i < 4; i++) {
            int ml = em0 + i * 16;
            int m  = m0 + ml;

            float gi = Gt[(0*16 + efi) * 65 + ml] + xwv[i][0] + bias_r[0];
            float gf = Gt[(1*16 + efi) * 65 + ml] + xwv[i][1] + bias_r[1];
            float gg = Gt[(2*16 + efi) * 65 + ml] + xwv[i][2] + bias_r[2];
            float go = Gt[(3*16 + efi) * 65 + ml] + xwv[i][3] + bias_r[3];

            float c  = fsigm(gf) * creg[i] + fsigm(gi) * ftanh(gg);
            float hv = fsigm(go) * ftanh(c);
            creg[i] = c;
            hvv[i] = hv;

            houtp[(size_t)m * FH + feat] = __float2half(hv);
        }

        __threadfence();
        __syncthreads();
        if (tid == 0) atomicAdd(ctr, 1u);

        #pragma unroll
        for (int i = 0; i < 4; i++) {
            int m = m0 + em0 + i * 16;
            out[((size_t)m * LT + t) * FH + feat] = hvv[i];
            if (t == LT - 1) {
                out[(size_t)NB * LT * FH + (size_t)m * FH + feat]           = hvv[i];
                out[(size_t)NB * LT * FH + NB * FH + (size_t)m * FH + feat] = creg[i];
            }
        }
    }
}

// ---------------- launch ----------------
extern "C" void kernel_launch(void* const* d_in, const int* in_sizes, int n_in,
                              void* d_out, int out_size)
{
    const float* src     = (const float*)d_in[0];
    const float* W_pre   = (const float*)d_in[1];
    const float* b_pre   = (const float*)d_in[2];
    const float* W_gat   = (const float*)d_in[3];
    const float* att_src = (const float*)d_in[4];
    const float* att_dst = (const float*)d_in[5];
    const float* b_gat   = (const float*)d_in[6];
    const float* W_ih    = (const float*)d_in[7];
    const float* W_hh    = (const float*)d_in[8];
    const float* b_ih    = (const float*)d_in[9];
    const float* b_hh    = (const float*)d_in[10];
    float* out = (float*)d_out;

    __half *Xp, *Wp;
    cudaGetSymbolAddress((void**)&Xp,  g_Xp);
    cudaGetSymbolAddress((void**)&Wp,  g_Wp);

    cudaFuncSetAttribute(mega, cudaFuncAttributeMaxDynamicSharedMemorySize,
                         MEGA_SMEM);

    // 0) prep
    reset_flags<<<1, 256>>>();
    pack_w<<<(GG * FH + 255) / 256, 256>>>(W_ih, Wp);
    pack_whh<<<(unsigned)(((size_t)GG * FH + 255) / 256), 256>>>(W_hh);

    // 1) GAT -> fp16 X
    gat_kernel<<<BG / 8, 256>>>(src, W_pre, b_pre, W_gat, att_src, att_dst, b_gat, Xp);

    // 2) fused producer-GEMM + persistent-LSTM
    mega<<<NRB + NGB, 256, MEGA_SMEM>>>(b_ih, b_hh, out);
}